// round 13
// baseline (speedup 1.0000x reference)
#include <cuda_runtime.h>
#include <cstdint>

#define NPTS 131072
#define BGR  64
#define NPG  2048
#define KNN  10
#define HD   64
#define CONV_BLOCKS (NPTS / 32)      // 4096
#define FULLMASK 0xffffffffu
#define PAIRNORM_EPS 1e-5f
#define ZPAD 65                      // s_z row stride
#define WPAD 65                      // sW row stride

// spatial grid for kNN
#define GDIM  64
#define NCELL (GDIM * GDIM)          // 4096
#define XMIN  (-5.0f)
#define CELL  0.15625f               // 10/64
#define INVCELL 6.4f

// ---------------------------------------------------------------------------
// Device scratch
// ---------------------------------------------------------------------------
__device__ float2 d_spos[NPTS];             // positions sorted by cell
__device__ int    d_sidx[NPTS];             // slot -> original local idx
__device__ int    d_slotof[NPTS];           // original local idx -> slot
__device__ int    d_cellstart[BGR * (NCELL + 1)];
__device__ int    d_knn[NPTS * KNN];        // neighbor GLOBAL SLOTS, row = slot
__device__ float  d_Ya[NPTS * HD];          // Yraw layer-2, slot-indexed
__device__ float  d_Yb[NPTS * HD];          // Yraw layer-3, slot-indexed
__device__ float  d_partT[65 * CONV_BLOCKS];// transposed partials [feature][block]
__device__ float  d_sum[65];                // per-feature totals
__device__ float  d_mean[HD];
__device__ float  d_scaleInv;
__device__ float  d_beff[HD];
__device__ int    d_pool[BGR * HD];         // pooled max (float bits, z>=0)
__device__ unsigned d_rc;                   // redstat ticket (self-resetting)

// ---------------------------------------------------------------------------
// init: zero the pool accumulator
// ---------------------------------------------------------------------------
__global__ void init_kernel() {
    int i = blockIdx.x * blockDim.x + threadIdx.x;
    if (i < BGR * HD) d_pool[i] = 0;
}

// ---------------------------------------------------------------------------
// reorder: per-graph counting sort by 64x64 cell id (half the graphs per call).
// ---------------------------------------------------------------------------
__global__ __launch_bounds__(256) void reorder_kernel(const float2* __restrict__ pos,
                                                      int gofs) {
    __shared__ int hist[NCELL];
    __shared__ unsigned short skey[NPG];
    __shared__ int scanbuf[256];
    int g = gofs + blockIdx.x;
    int tid = threadIdx.x;
    int base = g * NPG;

    for (int c = tid; c < NCELL; c += 256) hist[c] = 0;
    __syncthreads();

    for (int t = tid; t < NPG; t += 256) {
        float2 p = pos[base + t];
        int cx = (int)((p.x - XMIN) * INVCELL);
        int cy = (int)((p.y - XMIN) * INVCELL);
        cx = cx < 0 ? 0 : (cx > GDIM - 1 ? GDIM - 1 : cx);
        cy = cy < 0 ? 0 : (cy > GDIM - 1 ? GDIM - 1 : cy);
        unsigned key = (unsigned)(cy * GDIM + cx);
        skey[t] = (unsigned short)key;
        atomicAdd(&hist[key], 1);
    }
    __syncthreads();

    int cb = tid * 16;
    int loc[16];
    int tot = 0;
#pragma unroll
    for (int i = 0; i < 16; i++) { loc[i] = hist[cb + i]; tot += loc[i]; }
    scanbuf[tid] = tot;
    __syncthreads();
    for (int off = 1; off < 256; off <<= 1) {
        int add = 0;
        if (tid >= off) add = scanbuf[tid - off];
        __syncthreads();
        scanbuf[tid] += add;
        __syncthreads();
    }
    int run = scanbuf[tid] - tot;
#pragma unroll
    for (int i = 0; i < 16; i++) {
        hist[cb + i] = run;
        run += loc[i];
    }
    __syncthreads();

    int* cs = d_cellstart + g * (NCELL + 1);
    for (int c = tid; c < NCELL; c += 256) cs[c] = hist[c];
    if (tid == 0) cs[NCELL] = NPG;
    __syncthreads();

    for (int t = tid; t < NPG; t += 256) {
        int key = skey[t];
        int rank = atomicAdd(&hist[key], 1);
        d_spos[base + rank] = pos[base + t];
        d_sidx[base + rank] = t;
        d_slotof[base + t] = rank;
    }
}

// ---------------------------------------------------------------------------
// kNN: WARP-COOPERATIVE expanding rect-ring search.
// The warp's 32 queries are contiguous slots (spatially adjacent). The warp
// computes their bounding box, then scans ONE shared candidate stream
// (rect-ring expansion of the box); every candidate address is uniform
// across the warp (smem broadcast), each lane tests it against its own
// query with the exact lexicographic (d2, original idx) rule.
// Termination: per-lane conservative scanned-boundary bound, warp ballot.
// ---------------------------------------------------------------------------
#define INS2(da, db, ia, ib) { \
    if ((db < da) || (db == da && ib < ia)) { \
        float _t = da; da = db; db = _t; int _u = ia; ia = ib; ib = _u; } }

__global__ __launch_bounds__(256) void knn_kernel() {
    __shared__ float2 spos[NPG];          // 16 KB
    __shared__ int    sidx[NPG];          // 8 KB
    __shared__ int    scs[NCELL + 1];     // 16 KB
    int g = blockIdx.x >> 3;
    int oct = blockIdx.x & 7;
    int base = g * NPG;
    int tid = threadIdx.x;
    int lane = tid & 31, wk = tid >> 5;

    for (int t = tid; t < NPG; t += 256) { spos[t] = d_spos[base + t]; sidx[t] = d_sidx[base + t]; }
    const int* gcs = d_cellstart + g * (NCELL + 1);
    for (int c = tid; c < NCELL + 1; c += 256) scs[c] = gcs[c];
    __syncthreads();

    int qw = wk * 8 + oct;                // interleaved query-warp (0..63)
    int r = qw * 32 + lane;               // this lane's query slot
    float2 q = spos[r];

    // warp bounding box of the 32 queries
    float bxlo = q.x, bxhi = q.x, bylo = q.y, byhi = q.y;
#pragma unroll
    for (int off = 16; off > 0; off >>= 1) {
        bxlo = fminf(bxlo, __shfl_xor_sync(FULLMASK, bxlo, off));
        bxhi = fmaxf(bxhi, __shfl_xor_sync(FULLMASK, bxhi, off));
        bylo = fminf(bylo, __shfl_xor_sync(FULLMASK, bylo, off));
        byhi = fmaxf(byhi, __shfl_xor_sync(FULLMASK, byhi, off));
    }
    int cx0 = (int)((bxlo - XMIN) * INVCELL);
    int cx1 = (int)((bxhi - XMIN) * INVCELL);
    int cy0 = (int)((bylo - XMIN) * INVCELL);
    int cy1 = (int)((byhi - XMIN) * INVCELL);
    cx0 = cx0 < 0 ? 0 : (cx0 > GDIM - 1 ? GDIM - 1 : cx0);
    cx1 = cx1 < 0 ? 0 : (cx1 > GDIM - 1 ? GDIM - 1 : cx1);
    cy0 = cy0 < 0 ? 0 : (cy0 > GDIM - 1 ? GDIM - 1 : cy0);
    cy1 = cy1 < 0 ? 0 : (cy1 > GDIM - 1 ? GDIM - 1 : cy1);

    const float INF = __int_as_float(0x7f800000);
    float s0 = INF, s1 = INF, s2 = INF, s3 = INF, s4 = INF;
    float s5 = INF, s6 = INF, s7 = INF, s8 = INF, s9 = INF;
    int n0 = 0x7fffffff, n1 = n0, n2 = n0, n3 = n0, n4 = n0;
    int n5 = n0, n6 = n0, n7 = n0, n8 = n0, n9 = n0;

    // uniform candidate stream: row [yy], cells xa..xb inclusive
#define SCANROW(YY, XA, XB) { \
    int _c = (YY) * GDIM; \
    int _p0 = scs[_c + (XA)]; \
    int _p1 = scs[_c + (XB) + 1]; \
    for (int _p = _p0; _p < _p1; _p++) { \
        float2 cp = spos[_p]; \
        float dx = q.x - cp.x; \
        float dy = q.y - cp.y; \
        float d2 = __fadd_rn(__fmul_rn(dx, dx), __fmul_rn(dy, dy)); \
        if (d2 <= s9 && _p != r) { \
            int oi = sidx[_p]; \
            if (d2 < s9 || oi < n9) { \
                s9 = d2; n9 = oi; \
                INS2(s8, s9, n8, n9); INS2(s7, s8, n7, n8); INS2(s6, s7, n6, n7); \
                INS2(s5, s6, n5, n6); INS2(s4, s5, n4, n5); INS2(s3, s4, n3, n4); \
                INS2(s2, s3, n2, n3); INS2(s1, s2, n1, n2); INS2(s0, s1, n0, n1); \
            } } } }

    for (int R = 0; R < GDIM; R++) {
        if (R >= 1) {
            // region scanned so far: rect expanded by (R-1)
            float lox = XMIN + (float)(cx0 - R + 1) * CELL;
            float hix = XMIN + (float)(cx1 + R) * CELL;
            float loy = XMIN + (float)(cy0 - R + 1) * CELL;
            float hiy = XMIN + (float)(cy1 + R) * CELL;
            float bnd = fminf(fminf(q.x - lox, hix - q.x), fminf(q.y - loy, hiy - q.y));
            bool done = (bnd > 0.f) && (bnd * bnd * 0.9999f > s9);
            if (__all_sync(FULLMASK, done)) break;
        }
        if (R == 0) {
            for (int yy = cy0; yy <= cy1; yy++) SCANROW(yy, cx0, cx1);
        } else {
            int xs0 = cx0 - R < 0 ? 0 : cx0 - R;
            int xs1 = cx1 + R > GDIM - 1 ? GDIM - 1 : cx1 + R;
            if (cy0 - R >= 0)        SCANROW(cy0 - R, xs0, xs1);
            if (cy1 + R <= GDIM - 1) SCANROW(cy1 + R, xs0, xs1);
            int ys0 = cy0 - R + 1 < 0 ? 0 : cy0 - R + 1;
            int ys1 = cy1 + R - 1 > GDIM - 1 ? GDIM - 1 : cy1 + R - 1;
            if (cx0 - R >= 0)
                for (int yy = ys0; yy <= ys1; yy++) SCANROW(yy, cx0 - R, cx0 - R);
            if (cx1 + R <= GDIM - 1)
                for (int yy = ys0; yy <= ys1; yy++) SCANROW(yy, cx1 + R, cx1 + R);
        }
    }

    const int* so = d_slotof + base;
    int* op = d_knn + (base + r) * KNN;
    op[0] = base + so[n0]; op[1] = base + so[n1]; op[2] = base + so[n2];
    op[3] = base + so[n3]; op[4] = base + so[n4]; op[5] = base + so[n5];
    op[6] = base + so[n6]; op[7] = base + so[n7]; op[8] = base + so[n8];
    op[9] = base + so[n9];
}

// ---------------------------------------------------------------------------
// block stats -> TRANSPOSED partials d_partT[feature][block]
// ---------------------------------------------------------------------------
__device__ __forceinline__ void block_stats(const float* s_z, float* s_red, int blockId) {
    int tid = threadIdx.x;
    if (tid < HD) {
        float s = 0.f, sq = 0.f;
#pragma unroll
        for (int r = 0; r < 32; r++) {
            float v = s_z[r * ZPAD + tid];
            s += v;
            sq = fmaf(v, v, sq);
        }
        d_partT[tid * CONV_BLOCKS + blockId] = s;
        s_red[tid] = sq;
    }
    __syncthreads();
    if (tid < 32) {
        float v = s_red[tid] + s_red[tid + 32];
#pragma unroll
        for (int off = 16; off > 0; off >>= 1)
            v += __shfl_down_sync(FULLMASK, v, off);
        if (tid == 0) d_partT[64 * CONV_BLOCKS + blockId] = v;
    }
}

// ---------------------------------------------------------------------------
// redstat: 65 blocks, coalesced column reduce; last block folds mean/inv/beff
// ---------------------------------------------------------------------------
__global__ __launch_bounds__(256) void redstat_kernel(const float* __restrict__ Wnext,
                                                      const float* __restrict__ bnext) {
    __shared__ float sred[256];
    __shared__ float smean[64];
    __shared__ int   s_last;
    int f = blockIdx.x;              // 0..64
    int tid = threadIdx.x;

    const float* col = d_partT + f * CONV_BLOCKS;
    float s = 0.f;
#pragma unroll
    for (int k = 0; k < CONV_BLOCKS / 256; k++) s += col[tid + k * 256];
    sred[tid] = s;
    __syncthreads();
    if (tid < 128) sred[tid] += sred[tid + 128];
    __syncthreads();
    if (tid < 64) sred[tid] += sred[tid + 64];
    __syncthreads();
    if (tid < 32) {
        float v = sred[tid] + sred[tid + 32];
#pragma unroll
        for (int off = 16; off > 0; off >>= 1)
            v += __shfl_down_sync(FULLMASK, v, off);
        if (tid == 0) d_sum[f] = v;
    }
    __threadfence();
    if (tid == 0) {
        unsigned t = atomicAdd(&d_rc, 1u);
        s_last = (t == 64u);
    }
    __syncthreads();
    if (!s_last) return;

    if (tid < 64) {
        float mean = d_sum[tid] * (1.0f / (float)NPTS);
        smean[tid] = mean;
        d_mean[tid] = mean;
    }
    __syncthreads();
    if (tid == 0) {
        float sq = d_sum[64];
        float ms = 0.f;
#pragma unroll 4
        for (int k = 0; k < 64; k++) ms = fmaf(smean[k], smean[k], ms);
        float denom = sq * (1.0f / (float)NPTS) - ms;
        d_scaleInv = 1.0f / sqrtf(PAIRNORM_EPS + denom);
        d_rc = 0;                    // reset for next redstat instance
    }
    __syncthreads();
    if (Wnext != nullptr && tid < 64) {
        float inv = d_scaleInv;
        float acc = 0.f;
#pragma unroll 4
        for (int k = 0; k < 64; k++) acc = fmaf(smean[k], Wnext[k * HD + tid], acc);
        d_beff[tid] = bnext[tid] - inv * acc;
    }
}

// ---------------------------------------------------------------------------
// split-tf32 mma epilogue: Yout[32x64] = s_z[32x64] @ W[64x64].
// x = hi + lo (hi = tf32(x), lo = tf32(x - hi));
// C += Ahi*Bhi + Ahi*Blo + Alo*Bhi   (lo*lo dropped, ~1e-8 relative)
// ---------------------------------------------------------------------------
__device__ __forceinline__ uint32_t f2tf32(float x) {
    uint32_t r;
    asm("cvt.rna.tf32.f32 %0, %1;" : "=r"(r) : "f"(x));
    return r;
}

__device__ __forceinline__ void mma_tf32(float* c, uint32_t a0, uint32_t a1,
                                         uint32_t a2, uint32_t a3,
                                         uint32_t b0, uint32_t b1) {
    asm volatile(
        "mma.sync.aligned.m16n8k8.row.col.f32.tf32.tf32.f32 "
        "{%0,%1,%2,%3}, {%4,%5,%6,%7}, {%8,%9}, {%0,%1,%2,%3};"
        : "+f"(c[0]), "+f"(c[1]), "+f"(c[2]), "+f"(c[3])
        : "r"(a0), "r"(a1), "r"(a2), "r"(a3), "r"(b0), "r"(b1));
}

__device__ __forceinline__ void epilogue_mma(const float* s_z,
                                             const uint32_t* sWhi,
                                             const uint32_t* sWlo,
                                             float* Yout, int nodebase) {
    int lane = threadIdx.x & 31;
    int w = threadIdx.x >> 5;        // 0..7
    int rt = w & 1;                  // row tile (16 rows)
    int nt0 = (w >> 1) * 2;          // first of two col tiles (8 cols each)
    int grp = lane >> 2;             // 0..7
    int idx = lane & 3;              // 0..3
    float c0[4] = {0.f, 0.f, 0.f, 0.f};
    float c1[4] = {0.f, 0.f, 0.f, 0.f};

#pragma unroll
    for (int ks = 0; ks < 8; ks++) {
        int k0 = ks * 8;
        int ar = rt * 16 + grp;
        float z0 = s_z[ar * ZPAD + k0 + idx];
        float z1 = s_z[(ar + 8) * ZPAD + k0 + idx];
        float z2 = s_z[ar * ZPAD + k0 + idx + 4];
        float z3 = s_z[(ar + 8) * ZPAD + k0 + idx + 4];
        uint32_t h0 = f2tf32(z0), h1 = f2tf32(z1), h2 = f2tf32(z2), h3 = f2tf32(z3);
        uint32_t l0 = f2tf32(z0 - __uint_as_float(h0));
        uint32_t l1 = f2tf32(z1 - __uint_as_float(h1));
        uint32_t l2 = f2tf32(z2 - __uint_as_float(h2));
        uint32_t l3 = f2tf32(z3 - __uint_as_float(h3));

        int nA = nt0 * 8 + grp;
        uint32_t bh0 = sWhi[(k0 + idx) * WPAD + nA];
        uint32_t bh1 = sWhi[(k0 + idx + 4) * WPAD + nA];
        uint32_t bl0 = sWlo[(k0 + idx) * WPAD + nA];
        uint32_t bl1 = sWlo[(k0 + idx + 4) * WPAD + nA];
        mma_tf32(c0, h0, h1, h2, h3, bh0, bh1);
        mma_tf32(c0, h0, h1, h2, h3, bl0, bl1);
        mma_tf32(c0, l0, l1, l2, l3, bh0, bh1);

        int nB = (nt0 + 1) * 8 + grp;
        uint32_t ch0 = sWhi[(k0 + idx) * WPAD + nB];
        uint32_t ch1 = sWhi[(k0 + idx + 4) * WPAD + nB];
        uint32_t cl0 = sWlo[(k0 + idx) * WPAD + nB];
        uint32_t cl1 = sWlo[(k0 + idx + 4) * WPAD + nB];
        mma_tf32(c1, h0, h1, h2, h3, ch0, ch1);
        mma_tf32(c1, h0, h1, h2, h3, cl0, cl1);
        mma_tf32(c1, l0, l1, l2, l3, ch0, ch1);
    }

    int row = rt * 16 + grp;
    int colA = nt0 * 8 + idx * 2;
    int colB = (nt0 + 1) * 8 + idx * 2;
    *(float2*)(Yout + (nodebase + row) * HD + colA)       = make_float2(c0[0], c0[1]);
    *(float2*)(Yout + (nodebase + row + 8) * HD + colA)   = make_float2(c0[2], c0[3]);
    *(float2*)(Yout + (nodebase + row) * HD + colB)       = make_float2(c1[0], c1[1]);
    *(float2*)(Yout + (nodebase + row + 8) * HD + colB)   = make_float2(c1[2], c1[3]);
}

// staged padded weight split: hi = tf32(w), lo = tf32(w - hi)
__device__ __forceinline__ void load_W_split(uint32_t* sWhi, uint32_t* sWlo,
                                             const float* W) {
    int tid = threadIdx.x;
    for (int i = tid; i < HD * HD; i += 256) {
        float w = W[i];
        uint32_t hi = f2tf32(w);
        uint32_t lo = f2tf32(w - __uint_as_float(hi));
        int o = (i >> 6) * WPAD + (i & 63);
        sWhi[o] = hi;
        sWlo[o] = lo;
    }
}

// ---------------------------------------------------------------------------
// convA (layer 1): msg = rel @ W1 + b1, max + relu; stats; mma epilogue -> d_Ya
// ---------------------------------------------------------------------------
__global__ __launch_bounds__(256) void convA_kernel(const float* __restrict__ W1,
                                                    const float* __restrict__ b1,
                                                    const float* __restrict__ W2) {
    __shared__ float    s_z[32 * ZPAD];
    __shared__ uint32_t sWhi[HD * WPAD];
    __shared__ uint32_t sWlo[HD * WPAD];
    __shared__ float2   s_rel[8][KNN];
    __shared__ float    s_red[64];
    int tid = threadIdx.x, lane = tid & 31, wid = tid >> 5;
    int f0 = lane * 2, f1 = f0 + 1;
    float wx0 = W1[f0],      wx1 = W1[f1];
    float wy0 = W1[HD + f0], wy1 = W1[HD + f1];
    float bb0 = b1[f0],      bb1 = b1[f1];
    int nodebase = blockIdx.x * 32;

    load_W_split(sWhi, sWlo, W2);

    for (int it = 0; it < 4; it++) {
        int node = nodebase + wid * 4 + it;
        float2 pi = d_spos[node];
        __syncwarp();
        if (lane < KNN) {
            int jj = d_knn[node * KNN + lane];
            float2 pj = d_spos[jj];
            s_rel[wid][lane] = make_float2(pj.x - pi.x, pj.y - pi.y);
        }
        __syncwarp();
        float m0 = bb0, m1 = bb1;                // self edge rel=0
#pragma unroll
        for (int e = 0; e < KNN; e++) {
            float2 rel = s_rel[wid][e];
            m0 = fmaxf(m0, fmaf(rel.x, wx0, fmaf(rel.y, wy0, bb0)));
            m1 = fmaxf(m1, fmaf(rel.x, wx1, fmaf(rel.y, wy1, bb1)));
        }
        int r = wid * 4 + it;
        s_z[r * ZPAD + f0] = fmaxf(m0, 0.f);
        s_z[r * ZPAD + f1] = fmaxf(m1, 0.f);
    }
    __syncthreads();
    block_stats(s_z, s_red, blockIdx.x);
    __syncthreads();
    epilogue_mma(s_z, sWhi, sWlo, d_Ya, nodebase);
}

// ---------------------------------------------------------------------------
// convB (layer 2): msg = inv*Yraw[j] + rel @ Wr + beff; stats; mma -> d_Yb
// ---------------------------------------------------------------------------
__global__ __launch_bounds__(256) void convB_kernel(const float* __restrict__ W2,
                                                    const float* __restrict__ W3) {
    __shared__ float    s_z[32 * ZPAD];
    __shared__ uint32_t sWhi[HD * WPAD];
    __shared__ uint32_t sWlo[HD * WPAD];
    __shared__ float2   s_rel[8][KNN];
    __shared__ int      s_j[8][KNN];
    __shared__ float    s_red[64];
    int tid = threadIdx.x, lane = tid & 31, wid = tid >> 5;
    int f0 = lane * 2, f1 = f0 + 1;
    float wx0 = W2[64 * HD + f0], wx1 = W2[64 * HD + f1];
    float wy0 = W2[65 * HD + f0], wy1 = W2[65 * HD + f1];
    float be0 = d_beff[f0], be1 = d_beff[f1];
    float inv = d_scaleInv;
    int nodebase = blockIdx.x * 32;

    load_W_split(sWhi, sWlo, W3);

    for (int it = 0; it < 4; it++) {
        int node = nodebase + wid * 4 + it;
        float2 pi = d_spos[node];
        __syncwarp();
        if (lane < KNN) {
            int jj = d_knn[node * KNN + lane];
            float2 pj = d_spos[jj];
            s_rel[wid][lane] = make_float2(pj.x - pi.x, pj.y - pi.y);
            s_j[wid][lane] = jj;
        }
        __syncwarp();
        float2 ys = *(const float2*)(d_Ya + node * HD + f0);
        float m0 = fmaf(inv, ys.x, be0), m1 = fmaf(inv, ys.y, be1);
#pragma unroll
        for (int e = 0; e < KNN; e++) {
            float2 rel = s_rel[wid][e];
            int j = s_j[wid][e];
            float2 yv = *(const float2*)(d_Ya + j * HD + f0);
            m0 = fmaxf(m0, fmaf(inv, yv.x, fmaf(rel.x, wx0, fmaf(rel.y, wy0, be0))));
            m1 = fmaxf(m1, fmaf(inv, yv.y, fmaf(rel.x, wx1, fmaf(rel.y, wy1, be1))));
        }
        int r = wid * 4 + it;
        s_z[r * ZPAD + f0] = fmaxf(m0, 0.f);
        s_z[r * ZPAD + f1] = fmaxf(m1, 0.f);
    }
    __syncthreads();
    block_stats(s_z, s_red, blockIdx.x);
    __syncthreads();
    epilogue_mma(s_z, sWhi, sWlo, d_Yb, nodebase);
}

// ---------------------------------------------------------------------------
// convC (layer 3): gather d_Yb; stats; per-graph max pool
// ---------------------------------------------------------------------------
__global__ __launch_bounds__(256) void convC_kernel(const float* __restrict__ W3) {
    __shared__ float  s_z[32 * ZPAD];
    __shared__ float2 s_rel[8][KNN];
    __shared__ int    s_j[8][KNN];
    __shared__ float  s_red[64];
    int tid = threadIdx.x, lane = tid & 31, wid = tid >> 5;
    int f0 = lane * 2, f1 = f0 + 1;
    float wx0 = W3[64 * HD + f0], wx1 = W3[64 * HD + f1];
    float wy0 = W3[65 * HD + f0], wy1 = W3[65 * HD + f1];
    float be0 = d_beff[f0], be1 = d_beff[f1];
    float inv = d_scaleInv;
    int nodebase = blockIdx.x * 32;

    for (int it = 0; it < 4; it++) {
        int node = nodebase + wid * 4 + it;
        float2 pi = d_spos[node];
        __syncwarp();
        if (lane < KNN) {
            int jj = d_knn[node * KNN + lane];
            float2 pj = d_spos[jj];
            s_rel[wid][lane] = make_float2(pj.x - pi.x, pj.y - pi.y);
            s_j[wid][lane] = jj;
        }
        __syncwarp();
        float2 ys = *(const float2*)(d_Yb + node * HD + f0);
        float m0 = fmaf(inv, ys.x, be0), m1 = fmaf(inv, ys.y, be1);
#pragma unroll
        for (int e = 0; e < KNN; e++) {
            float2 rel = s_rel[wid][e];
            int j = s_j[wid][e];
            float2 yv = *(const float2*)(d_Yb + j * HD + f0);
            m0 = fmaxf(m0, fmaf(inv, yv.x, fmaf(rel.x, wx0, fmaf(rel.y, wy0, be0))));
            m1 = fmaxf(m1, fmaf(inv, yv.y, fmaf(rel.x, wx1, fmaf(rel.y, wy1, be1))));
        }
        int r = wid * 4 + it;
        s_z[r * ZPAD + f0] = fmaxf(m0, 0.f);
        s_z[r * ZPAD + f1] = fmaxf(m1, 0.f);
    }
    __syncthreads();
    block_stats(s_z, s_red, blockIdx.x);
    if (tid < HD) {
        float m = s_z[tid];
#pragma unroll
        for (int r = 1; r < 32; r++) m = fmaxf(m, s_z[r * ZPAD + tid]);
        int g = blockIdx.x >> 6;
        atomicMax(&d_pool[g * HD + tid], __float_as_int(m));
    }
}

// ---------------------------------------------------------------------------
// head: normalize pooled max on the fly; MLP -> out[64,2]
// ---------------------------------------------------------------------------
__global__ __launch_bounds__(128) void head_kernel(const float* __restrict__ Wl1,
                                                   const float* __restrict__ bl1,
                                                   const float* __restrict__ Wl2,
                                                   const float* __restrict__ bl2,
                                                   float* __restrict__ out) {
    __shared__ float t1[BGR * HD];
    __shared__ float sW[HD * HD];
    __shared__ float s_mean[64];
    int tid = threadIdx.x;
    float inv = d_scaleInv;

    if (tid < HD) s_mean[tid] = d_mean[tid];
    const float4* W4 = (const float4*)Wl1;
    float4* sW4 = (float4*)sW;
    for (int i = tid; i < HD * HD / 4; i += 128) sW4[i] = W4[i];
    __syncthreads();

    int g = tid >> 1, half = tid & 1;
    float acc[32];
#pragma unroll
    for (int c = 0; c < 32; c++) acc[c] = bl1[half * 32 + c];
    for (int k = 0; k < HD; k++) {
        float h = (__int_as_float(d_pool[g * HD + k]) - s_mean[k]) * inv;
        const float* wrow = sW + k * HD + half * 32;
#pragma unroll
        for (int c = 0; c < 32; c++) acc[c] = fmaf(h, wrow[c], acc[c]);
    }
#pragma unroll
    for (int c = 0; c < 32; c++) t1[g * HD + half * 32 + c] = fmaxf(acc[c], 0.f);
    __syncthreads();

    int gg = tid >> 1, o = tid & 1;
    float s = bl2[o];
    for (int k = 0; k < HD; k++) s = fmaf(t1[gg * HD + k], Wl2[k * 2 + o], s);
    out[gg * 2 + o] = s;
}

// ---------------------------------------------------------------------------
// launch — ncu captures launch index 3 => knn_kernel
// ---------------------------------------------------------------------------
extern "C" void kernel_launch(void* const* d_in, const int* in_sizes, int n_in,
                              void* d_out, int out_size) {
    const float2* pos = (const float2*)d_in[0];
    const float* W1  = (const float*)d_in[2];
    const float* b1  = (const float*)d_in[3];
    const float* W2  = (const float*)d_in[4];
    const float* b2  = (const float*)d_in[5];
    const float* W3  = (const float*)d_in[6];
    const float* b3  = (const float*)d_in[7];
    const float* Wl1 = (const float*)d_in[8];
    const float* bl1 = (const float*)d_in[9];
    const float* Wl2 = (const float*)d_in[10];
    const float* bl2 = (const float*)d_in[11];
    float* out = (float*)d_out;

    init_kernel<<<16, 256>>>();                        // 0
    reorder_kernel<<<BGR / 2, 256>>>(pos, 0);          // 1
    reorder_kernel<<<BGR / 2, 256>>>(pos, BGR / 2);    // 2
    knn_kernel<<<BGR * 8, 256>>>();                    // 3  <- profiled

    convA_kernel<<<CONV_BLOCKS, 256>>>(W1, b1, W2);    // 4
    redstat_kernel<<<65, 256>>>(W2, b2);               // 5
    convB_kernel<<<CONV_BLOCKS, 256>>>(W2, W3);        // 6
    redstat_kernel<<<65, 256>>>(W3, b3);               // 7
    convC_kernel<<<CONV_BLOCKS, 256>>>(W3);            // 8
    redstat_kernel<<<65, 256>>>(nullptr, nullptr);     // 9
    head_kernel<<<1, 128>>>(Wl1, bl1, Wl2, bl2, out);  // 10
}

// round 14
// speedup vs baseline: 1.3024x; 1.3024x over previous
#include <cuda_runtime.h>
#include <cstdint>

#define NPTS 131072
#define BGR  64
#define NPG  2048
#define KNN  10
#define HD   64
#define CONV_BLOCKS (NPTS / 32)      // 4096
#define FULLMASK 0xffffffffu
#define PAIRNORM_EPS 1e-5f
#define ZPAD 65                      // s_z row stride
#define WPAD 65                      // sW row stride

// spatial grid for kNN
#define GDIM  64
#define NCELL (GDIM * GDIM)          // 4096
#define XMIN  (-5.0f)
#define CELL  0.15625f               // 10/64
#define INVCELL 6.4f

// fixed-point stat accumulator scales (validated r5: rel_err 9.3e-7)
#define S1 67108864.0f               // 2^26 for feature sums
#define S2 1048576.0f                // 2^20 for sum of squares

// ---------------------------------------------------------------------------
// Device scratch
// ---------------------------------------------------------------------------
__device__ float2 d_spos[NPTS];             // positions sorted by cell
__device__ int    d_sidx[NPTS];             // slot -> original local idx
__device__ int    d_slotof[NPTS];           // original local idx -> slot
__device__ int    d_cellstart[BGR * (NCELL + 1)];
__device__ int    d_knn[NPTS * KNN];        // neighbor GLOBAL SLOTS, row = slot
__device__ float  d_Ya[NPTS * HD];          // Yraw layer-2, slot-indexed
__device__ float  d_Yb[NPTS * HD];          // Yraw layer-3, slot-indexed
__device__ unsigned long long d_acc[3][65]; // fixed-point stats: 64 sums + sumsq
__device__ int    d_pool[BGR * HD];         // pooled max (float bits, z>=0)

// ---------------------------------------------------------------------------
// reorder: per-graph counting sort by 64x64 cell id (single launch).
// Block 0 zeroes pool + stat accumulators.
// Within-cell order nondeterministic (atomics) but kNN selection is
// order-independent (lexicographic (d2, original idx)) -> deterministic.
// ---------------------------------------------------------------------------
__global__ __launch_bounds__(256) void reorder_kernel(const float2* __restrict__ pos) {
    __shared__ int hist[NCELL];
    __shared__ unsigned short skey[NPG];
    __shared__ int scanbuf[256];
    int g = blockIdx.x;
    int tid = threadIdx.x;
    int base = g * NPG;

    if (g == 0) {
        for (int i = tid; i < BGR * HD; i += 256) d_pool[i] = 0;
        if (tid < 65) {
            d_acc[0][tid] = 0ull;
            d_acc[1][tid] = 0ull;
            d_acc[2][tid] = 0ull;
        }
    }

    for (int c = tid; c < NCELL; c += 256) hist[c] = 0;
    __syncthreads();

    for (int t = tid; t < NPG; t += 256) {
        float2 p = pos[base + t];
        int cx = (int)((p.x - XMIN) * INVCELL);
        int cy = (int)((p.y - XMIN) * INVCELL);
        cx = cx < 0 ? 0 : (cx > GDIM - 1 ? GDIM - 1 : cx);
        cy = cy < 0 ? 0 : (cy > GDIM - 1 ? GDIM - 1 : cy);
        unsigned key = (unsigned)(cy * GDIM + cx);
        skey[t] = (unsigned short)key;
        atomicAdd(&hist[key], 1);
    }
    __syncthreads();

    int cb = tid * 16;
    int loc[16];
    int tot = 0;
#pragma unroll
    for (int i = 0; i < 16; i++) { loc[i] = hist[cb + i]; tot += loc[i]; }
    scanbuf[tid] = tot;
    __syncthreads();
    for (int off = 1; off < 256; off <<= 1) {
        int add = 0;
        if (tid >= off) add = scanbuf[tid - off];
        __syncthreads();
        scanbuf[tid] += add;
        __syncthreads();
    }
    int run = scanbuf[tid] - tot;
#pragma unroll
    for (int i = 0; i < 16; i++) {
        hist[cb + i] = run;
        run += loc[i];
    }
    __syncthreads();

    int* cs = d_cellstart + g * (NCELL + 1);
    for (int c = tid; c < NCELL; c += 256) cs[c] = hist[c];
    if (tid == 0) cs[NCELL] = NPG;
    __syncthreads();

    for (int t = tid; t < NPG; t += 256) {
        int key = skey[t];
        int rank = atomicAdd(&hist[key], 1);
        d_spos[base + rank] = pos[base + t];
        d_sidx[base + rank] = t;
        d_slotof[base + t] = rank;
    }
}

// ---------------------------------------------------------------------------
// kNN (round-9 champion, thrice-reproduced at 127us): single thread/query,
// warp-interleaved blocks, exact top-10 by lexicographic (d2, original idx).
// ---------------------------------------------------------------------------
#define INS2(da, db, ia, ib) { \
    if ((db < da) || (db == da && ib < ia)) { \
        float _t = da; da = db; db = _t; int _u = ia; ia = ib; ib = _u; } }

__global__ __launch_bounds__(256) void knn_kernel() {
    __shared__ float2 spos[NPG];          // 16 KB
    __shared__ int    sidx[NPG];          // 8 KB
    __shared__ int    scs[NCELL + 1];     // 16 KB
    int g = blockIdx.x >> 3;
    int oct = blockIdx.x & 7;
    int base = g * NPG;
    int tid = threadIdx.x;
    int lane = tid & 31, wk = tid >> 5;

    for (int t = tid; t < NPG; t += 256) { spos[t] = d_spos[base + t]; sidx[t] = d_sidx[base + t]; }
    const int* gcs = d_cellstart + g * (NCELL + 1);
    for (int c = tid; c < NCELL + 1; c += 256) scs[c] = gcs[c];
    __syncthreads();

    int qw = wk * 8 + oct;                // interleaved query-warp (0..63)
    int r = qw * 32 + lane;               // query slot
    float2 q = spos[r];

    int cx = (int)((q.x - XMIN) * INVCELL);
    int cy = (int)((q.y - XMIN) * INVCELL);
    cx = cx < 0 ? 0 : (cx > GDIM - 1 ? GDIM - 1 : cx);
    cy = cy < 0 ? 0 : (cy > GDIM - 1 ? GDIM - 1 : cy);

    const float INF = __int_as_float(0x7f800000);
    float s0 = INF, s1 = INF, s2 = INF, s3 = INF, s4 = INF;
    float s5 = INF, s6 = INF, s7 = INF, s8 = INF, s9 = INF;
    int n0 = 0x7fffffff, n1 = n0, n2 = n0, n3 = n0, n4 = n0;
    int n5 = n0, n6 = n0, n7 = n0, n8 = n0, n9 = n0;

#define SCANRANGE(P0, P1) { \
    for (int _p = (P0); _p < (P1); _p++) { \
        float2 cp = spos[_p]; \
        float dx = q.x - cp.x; \
        float dy = q.y - cp.y; \
        float d2 = __fadd_rn(__fmul_rn(dx, dx), __fmul_rn(dy, dy)); \
        if (d2 <= s9 && _p != r) { \
            int oi = sidx[_p]; \
            if (d2 < s9 || oi < n9) { \
                s9 = d2; n9 = oi; \
                INS2(s8, s9, n8, n9); INS2(s7, s8, n7, n8); INS2(s6, s7, n6, n7); \
                INS2(s5, s6, n5, n6); INS2(s4, s5, n4, n5); INS2(s3, s4, n3, n4); \
                INS2(s2, s3, n2, n3); INS2(s1, s2, n1, n2); INS2(s0, s1, n0, n1); \
            } } } }

    for (int R = 0; R < GDIM; R++) {
        if (R >= 1) {
            float lox = XMIN + (float)(cx - R + 1) * CELL;
            float hix = XMIN + (float)(cx + R) * CELL;
            float loy = XMIN + (float)(cy - R + 1) * CELL;
            float hiy = XMIN + (float)(cy + R) * CELL;
            float bnd = fminf(fminf(q.x - lox, hix - q.x), fminf(q.y - loy, hiy - q.y));
            if (bnd > 0.f && bnd * bnd * 0.9999f > s9) break;
        }
        if (R == 0) {
            int c = cy * GDIM + cx;
            SCANRANGE(scs[c], scs[c + 1]);
        } else {
            int x0 = cx - R < 0 ? 0 : cx - R;
            int x1 = cx + R > GDIM - 1 ? GDIM - 1 : cx + R;
            if (cy - R >= 0) {
                int c = (cy - R) * GDIM;
                SCANRANGE(scs[c + x0], scs[c + x1 + 1]);
            }
            if (cy + R <= GDIM - 1) {
                int c = (cy + R) * GDIM;
                SCANRANGE(scs[c + x0], scs[c + x1 + 1]);
            }
            int y0 = cy - R + 1 < 0 ? 0 : cy - R + 1;
            int y1 = cy + R - 1 > GDIM - 1 ? GDIM - 1 : cy + R - 1;
            if (cx - R >= 0) {
                for (int yy = y0; yy <= y1; yy++) {
                    int c = yy * GDIM + cx - R;
                    SCANRANGE(scs[c], scs[c + 1]);
                }
            }
            if (cx + R <= GDIM - 1) {
                for (int yy = y0; yy <= y1; yy++) {
                    int c = yy * GDIM + cx + R;
                    SCANRANGE(scs[c], scs[c + 1]);
                }
            }
        }
    }

    const int* so = d_slotof + base;
    int* op = d_knn + (base + r) * KNN;
    op[0] = base + so[n0]; op[1] = base + so[n1]; op[2] = base + so[n2];
    op[3] = base + so[n3]; op[4] = base + so[n4]; op[5] = base + so[n5];
    op[6] = base + so[n6]; op[7] = base + so[n7]; op[8] = base + so[n8];
    op[9] = base + so[n9];
}

// ---------------------------------------------------------------------------
// block stats -> fixed-point global accumulators (deterministic int atomics)
// ---------------------------------------------------------------------------
__device__ __forceinline__ void block_stats_acc(const float* s_z, float* s_red, int set) {
    int tid = threadIdx.x;
    if (tid < HD) {
        float s = 0.f, sq = 0.f;
#pragma unroll
        for (int r = 0; r < 32; r++) {
            float v = s_z[r * ZPAD + tid];
            s += v;
            sq = fmaf(v, v, sq);
        }
        atomicAdd(&d_acc[set][tid], (unsigned long long)(long long)llrintf(s * S1));
        s_red[tid] = sq;
    }
    __syncthreads();
    if (tid < 32) {
        float v = s_red[tid] + s_red[tid + 32];
#pragma unroll
        for (int off = 16; off > 0; off >>= 1)
            v += __shfl_down_sync(FULLMASK, v, off);
        if (tid == 0)
            atomicAdd(&d_acc[set][64], (unsigned long long)(long long)llrintf(v * S2));
    }
}

// ---------------------------------------------------------------------------
// stats prologue: mean/inv (+ beff if Wx given) from accumulator set
// ---------------------------------------------------------------------------
__device__ __forceinline__ void stats_prologue(int set, const float* Wx, const float* bn,
                                               float* s_mean, float* s_beff, float* s_inv) {
    int tid = threadIdx.x;
    if (tid < HD)
        s_mean[tid] = (float)(long long)d_acc[set][tid] * (1.0f / S1) * (1.0f / (float)NPTS);
    __syncthreads();
    if (tid == 0) {
        float sq = (float)(long long)d_acc[set][64] * (1.0f / S2);
        float ms = 0.f;
#pragma unroll 4
        for (int f = 0; f < 64; f++) ms = fmaf(s_mean[f], s_mean[f], ms);
        float denom = sq * (1.0f / (float)NPTS) - ms;
        s_inv[0] = 1.0f / sqrtf(PAIRNORM_EPS + denom);
    }
    __syncthreads();
    if (Wx != nullptr && tid < HD) {
        float inv = s_inv[0];
        float acc = 0.f;
#pragma unroll 4
        for (int k = 0; k < 64; k++) acc = fmaf(s_mean[k], Wx[k * HD + tid], acc);
        s_beff[tid] = bn[tid] - inv * acc;
    }
    __syncthreads();
}

// ---------------------------------------------------------------------------
// split-tf32 mma epilogue (validated r13: rel_err 1.1e-6):
// C += Ahi*Bhi + Ahi*Blo + Alo*Bhi
// ---------------------------------------------------------------------------
__device__ __forceinline__ uint32_t f2tf32(float x) {
    uint32_t r;
    asm("cvt.rna.tf32.f32 %0, %1;" : "=r"(r) : "f"(x));
    return r;
}

__device__ __forceinline__ void mma_tf32(float* c, uint32_t a0, uint32_t a1,
                                         uint32_t a2, uint32_t a3,
                                         uint32_t b0, uint32_t b1) {
    asm volatile(
        "mma.sync.aligned.m16n8k8.row.col.f32.tf32.tf32.f32 "
        "{%0,%1,%2,%3}, {%4,%5,%6,%7}, {%8,%9}, {%0,%1,%2,%3};"
        : "+f"(c[0]), "+f"(c[1]), "+f"(c[2]), "+f"(c[3])
        : "r"(a0), "r"(a1), "r"(a2), "r"(a3), "r"(b0), "r"(b1));
}

__device__ __forceinline__ void epilogue_mma(const float* s_z,
                                             const uint32_t* sWhi,
                                             const uint32_t* sWlo,
                                             float* Yout, int nodebase) {
    int lane = threadIdx.x & 31;
    int w = threadIdx.x >> 5;        // 0..7
    int rt = w & 1;                  // row tile (16 rows)
    int nt0 = (w >> 1) * 2;          // first of two col tiles (8 cols each)
    int grp = lane >> 2;             // 0..7
    int idx = lane & 3;              // 0..3
    float c0[4] = {0.f, 0.f, 0.f, 0.f};
    float c1[4] = {0.f, 0.f, 0.f, 0.f};

#pragma unroll
    for (int ks = 0; ks < 8; ks++) {
        int k0 = ks * 8;
        int ar = rt * 16 + grp;
        float z0 = s_z[ar * ZPAD + k0 + idx];
        float z1 = s_z[(ar + 8) * ZPAD + k0 + idx];
        float z2 = s_z[ar * ZPAD + k0 + idx + 4];
        float z3 = s_z[(ar + 8) * ZPAD + k0 + idx + 4];
        uint32_t h0 = f2tf32(z0), h1 = f2tf32(z1), h2 = f2tf32(z2), h3 = f2tf32(z3);
        uint32_t l0 = f2tf32(z0 - __uint_as_float(h0));
        uint32_t l1 = f2tf32(z1 - __uint_as_float(h1));
        uint32_t l2 = f2tf32(z2 - __uint_as_float(h2));
        uint32_t l3 = f2tf32(z3 - __uint_as_float(h3));

        int nA = nt0 * 8 + grp;
        uint32_t bh0 = sWhi[(k0 + idx) * WPAD + nA];
        uint32_t bh1 = sWhi[(k0 + idx + 4) * WPAD + nA];
        uint32_t bl0 = sWlo[(k0 + idx) * WPAD + nA];
        uint32_t bl1 = sWlo[(k0 + idx + 4) * WPAD + nA];
        mma_tf32(c0, h0, h1, h2, h3, bh0, bh1);
        mma_tf32(c0, h0, h1, h2, h3, bl0, bl1);
        mma_tf32(c0, l0, l1, l2, l3, bh0, bh1);

        int nB = (nt0 + 1) * 8 + grp;
        uint32_t ch0 = sWhi[(k0 + idx) * WPAD + nB];
        uint32_t ch1 = sWhi[(k0 + idx + 4) * WPAD + nB];
        uint32_t cl0 = sWlo[(k0 + idx) * WPAD + nB];
        uint32_t cl1 = sWlo[(k0 + idx + 4) * WPAD + nB];
        mma_tf32(c1, h0, h1, h2, h3, ch0, ch1);
        mma_tf32(c1, h0, h1, h2, h3, cl0, cl1);
        mma_tf32(c1, l0, l1, l2, l3, ch0, ch1);
    }

    int row = rt * 16 + grp;
    int colA = nt0 * 8 + idx * 2;
    int colB = (nt0 + 1) * 8 + idx * 2;
    *(float2*)(Yout + (nodebase + row) * HD + colA)       = make_float2(c0[0], c0[1]);
    *(float2*)(Yout + (nodebase + row + 8) * HD + colA)   = make_float2(c0[2], c0[3]);
    *(float2*)(Yout + (nodebase + row) * HD + colB)       = make_float2(c1[0], c1[1]);
    *(float2*)(Yout + (nodebase + row + 8) * HD + colB)   = make_float2(c1[2], c1[3]);
}

// staged padded weight split: hi = tf32(w), lo = tf32(w - hi)
__device__ __forceinline__ void load_W_split(uint32_t* sWhi, uint32_t* sWlo,
                                             const float* W) {
    int tid = threadIdx.x;
    for (int i = tid; i < HD * HD; i += 256) {
        float w = W[i];
        uint32_t hi = f2tf32(w);
        uint32_t lo = f2tf32(w - __uint_as_float(hi));
        int o = (i >> 6) * WPAD + (i & 63);
        sWhi[o] = hi;
        sWlo[o] = lo;
    }
}

// ---------------------------------------------------------------------------
// convA (layer 1): msg = rel @ W1 + b1, max + relu; stats -> acc[0];
//   split-tf32 epilogue Yraw2 = z @ W2x -> d_Ya
// ---------------------------------------------------------------------------
__global__ __launch_bounds__(256) void convA_kernel(const float* __restrict__ W1,
                                                    const float* __restrict__ b1,
                                                    const float* __restrict__ W2) {
    __shared__ float    s_z[32 * ZPAD];
    __shared__ uint32_t sWhi[HD * WPAD];
    __shared__ uint32_t sWlo[HD * WPAD];
    __shared__ float2   s_rel[8][KNN];
    __shared__ float    s_red[64];
    int tid = threadIdx.x, lane = tid & 31, wid = tid >> 5;
    int f0 = lane * 2, f1 = f0 + 1;
    float wx0 = W1[f0],      wx1 = W1[f1];
    float wy0 = W1[HD + f0], wy1 = W1[HD + f1];
    float bb0 = b1[f0],      bb1 = b1[f1];
    int nodebase = blockIdx.x * 32;

    load_W_split(sWhi, sWlo, W2);

    for (int it = 0; it < 4; it++) {
        int node = nodebase + wid * 4 + it;
        float2 pi = d_spos[node];
        __syncwarp();
        if (lane < KNN) {
            int jj = d_knn[node * KNN + lane];
            float2 pj = d_spos[jj];
            s_rel[wid][lane] = make_float2(pj.x - pi.x, pj.y - pi.y);
        }
        __syncwarp();
        float m0 = bb0, m1 = bb1;                // self edge rel=0
#pragma unroll
        for (int e = 0; e < KNN; e++) {
            float2 rel = s_rel[wid][e];
            m0 = fmaxf(m0, fmaf(rel.x, wx0, fmaf(rel.y, wy0, bb0)));
            m1 = fmaxf(m1, fmaf(rel.x, wx1, fmaf(rel.y, wy1, bb1)));
        }
        int r = wid * 4 + it;
        s_z[r * ZPAD + f0] = fmaxf(m0, 0.f);
        s_z[r * ZPAD + f1] = fmaxf(m1, 0.f);
    }
    __syncthreads();
    block_stats_acc(s_z, s_red, 0);
    __syncthreads();
    epilogue_mma(s_z, sWhi, sWlo, d_Ya, nodebase);
}

// ---------------------------------------------------------------------------
// convB (layer 2): prologue stats from acc[0]; gather d_Ya;
//   stats -> acc[1]; split-tf32 epilogue (W3) -> d_Yb
// ---------------------------------------------------------------------------
__global__ __launch_bounds__(256) void convB_kernel(const float* __restrict__ W2,
                                                    const float* __restrict__ b2,
                                                    const float* __restrict__ W3) {
    __shared__ float    s_z[32 * ZPAD];
    __shared__ uint32_t sWhi[HD * WPAD];
    __shared__ uint32_t sWlo[HD * WPAD];
    __shared__ float2   s_rel[8][KNN];
    __shared__ int      s_j[8][KNN];
    __shared__ float    s_red[64];
    __shared__ float    s_mean[64];
    __shared__ float    s_beff[64];
    __shared__ float    s_inv[1];
    int tid = threadIdx.x, lane = tid & 31, wid = tid >> 5;
    int f0 = lane * 2, f1 = f0 + 1;

    load_W_split(sWhi, sWlo, W3);
    stats_prologue(0, W2, b2, s_mean, s_beff, s_inv);

    float wx0 = W2[64 * HD + f0], wx1 = W2[64 * HD + f1];
    float wy0 = W2[65 * HD + f0], wy1 = W2[65 * HD + f1];
    float be0 = s_beff[f0], be1 = s_beff[f1];
    float inv = s_inv[0];
    int nodebase = blockIdx.x * 32;

    for (int it = 0; it < 4; it++) {
        int node = nodebase + wid * 4 + it;
        float2 pi = d_spos[node];
        __syncwarp();
        if (lane < KNN) {
            int jj = d_knn[node * KNN + lane];
            float2 pj = d_spos[jj];
            s_rel[wid][lane] = make_float2(pj.x - pi.x, pj.y - pi.y);
            s_j[wid][lane] = jj;
        }
        __syncwarp();
        float2 ys = *(const float2*)(d_Ya + node * HD + f0);
        float m0 = fmaf(inv, ys.x, be0), m1 = fmaf(inv, ys.y, be1);
#pragma unroll
        for (int e = 0; e < KNN; e++) {
            float2 rel = s_rel[wid][e];
            int j = s_j[wid][e];
            float2 yv = *(const float2*)(d_Ya + j * HD + f0);
            m0 = fmaxf(m0, fmaf(inv, yv.x, fmaf(rel.x, wx0, fmaf(rel.y, wy0, be0))));
            m1 = fmaxf(m1, fmaf(inv, yv.y, fmaf(rel.x, wx1, fmaf(rel.y, wy1, be1))));
        }
        int r = wid * 4 + it;
        s_z[r * ZPAD + f0] = fmaxf(m0, 0.f);
        s_z[r * ZPAD + f1] = fmaxf(m1, 0.f);
    }
    __syncthreads();
    block_stats_acc(s_z, s_red, 1);
    __syncthreads();
    epilogue_mma(s_z, sWhi, sWlo, d_Yb, nodebase);
}

// ---------------------------------------------------------------------------
// convC (layer 3): prologue stats from acc[1]; gather d_Yb;
//   stats -> acc[2]; per-graph max pool
// ---------------------------------------------------------------------------
__global__ __launch_bounds__(256) void convC_kernel(const float* __restrict__ W3,
                                                    const float* __restrict__ b3) {
    __shared__ float  s_z[32 * ZPAD];
    __shared__ float2 s_rel[8][KNN];
    __shared__ int    s_j[8][KNN];
    __shared__ float  s_red[64];
    __shared__ float  s_mean[64];
    __shared__ float  s_beff[64];
    __shared__ float  s_inv[1];
    int tid = threadIdx.x, lane = tid & 31, wid = tid >> 5;
    int f0 = lane * 2, f1 = f0 + 1;

    stats_prologue(1, W3, b3, s_mean, s_beff, s_inv);

    float wx0 = W3[64 * HD + f0], wx1 = W3[64 * HD + f1];
    float wy0 = W3[65 * HD + f0], wy1 = W3[65 * HD + f1];
    float be0 = s_beff[f0], be1 = s_beff[f1];
    float inv = s_inv[0];
    int nodebase = blockIdx.x * 32;

    for (int it = 0; it < 4; it++) {
        int node = nodebase + wid * 4 + it;
        float2 pi = d_spos[node];
        __syncwarp();
        if (lane < KNN) {
            int jj = d_knn[node * KNN + lane];
            float2 pj = d_spos[jj];
            s_rel[wid][lane] = make_float2(pj.x - pi.x, pj.y - pi.y);
            s_j[wid][lane] = jj;
        }
        __syncwarp();
        float2 ys = *(const float2*)(d_Yb + node * HD + f0);
        float m0 = fmaf(inv, ys.x, be0), m1 = fmaf(inv, ys.y, be1);
#pragma unroll
        for (int e = 0; e < KNN; e++) {
            float2 rel = s_rel[wid][e];
            int j = s_j[wid][e];
            float2 yv = *(const float2*)(d_Yb + j * HD + f0);
            m0 = fmaxf(m0, fmaf(inv, yv.x, fmaf(rel.x, wx0, fmaf(rel.y, wy0, be0))));
            m1 = fmaxf(m1, fmaf(inv, yv.y, fmaf(rel.x, wx1, fmaf(rel.y, wy1, be1))));
        }
        int r = wid * 4 + it;
        s_z[r * ZPAD + f0] = fmaxf(m0, 0.f);
        s_z[r * ZPAD + f1] = fmaxf(m1, 0.f);
    }
    __syncthreads();
    block_stats_acc(s_z, s_red, 2);
    if (tid < HD) {
        float m = s_z[tid];
#pragma unroll
        for (int r = 1; r < 32; r++) m = fmaxf(m, s_z[r * ZPAD + tid]);
        int g = blockIdx.x >> 6;
        atomicMax(&d_pool[g * HD + tid], __float_as_int(m));
    }
}

// ---------------------------------------------------------------------------
// head: stats from acc[2]; normalize pooled max on the fly; MLP -> out[64,2]
// ---------------------------------------------------------------------------
__global__ __launch_bounds__(128) void head_kernel(const float* __restrict__ Wl1,
                                                   const float* __restrict__ bl1,
                                                   const float* __restrict__ Wl2,
                                                   const float* __restrict__ bl2,
                                                   float* __restrict__ out) {
    __shared__ float t1[BGR * HD];
    __shared__ float sW[HD * HD];
    __shared__ float s_mean[64];
    __shared__ float s_inv[1];
    int tid = threadIdx.x;

    if (tid < HD)
        s_mean[tid] = (float)(long long)d_acc[2][tid] * (1.0f / S1) * (1.0f / (float)NPTS);
    const float4* W4 = (const float4*)Wl1;
    float4* sW4 = (float4*)sW;
    for (int i = tid; i < HD * HD / 4; i += 128) sW4[i] = W4[i];
    __syncthreads();
    if (tid == 0) {
        float sq = (float)(long long)d_acc[2][64] * (1.0f / S2);
        float ms = 0.f;
#pragma unroll 4
        for (int f = 0; f < 64; f++) ms = fmaf(s_mean[f], s_mean[f], ms);
        float denom = sq * (1.0f / (float)NPTS) - ms;
        s_inv[0] = 1.0f / sqrtf(PAIRNORM_EPS + denom);
    }
    __syncthreads();
    float inv = s_inv[0];

    int g = tid >> 1, half = tid & 1;
    float acc[32];
#pragma unroll
    for (int c = 0; c < 32; c++) acc[c] = bl1[half * 32 + c];
    for (int k = 0; k < HD; k++) {
        float h = (__int_as_float(d_pool[g * HD + k]) - s_mean[k]) * inv;
        const float* wrow = sW + k * HD + half * 32;
#pragma unroll
        for (int c = 0; c < 32; c++) acc[c] = fmaf(h, wrow[c], acc[c]);
    }
#pragma unroll
    for (int c = 0; c < 32; c++) t1[g * HD + half * 32 + c] = fmaxf(acc[c], 0.f);
    __syncthreads();

    int gg = tid >> 1, o = tid & 1;
    float s = bl2[o];
    for (int k = 0; k < HD; k++) s = fmaf(t1[gg * HD + k], Wl2[k * 2 + o], s);
    out[gg * 2 + o] = s;
}

// ---------------------------------------------------------------------------
// launch (6 kernels; capture index 3 = convB, first profile of that kernel)
// ---------------------------------------------------------------------------
extern "C" void kernel_launch(void* const* d_in, const int* in_sizes, int n_in,
                              void* d_out, int out_size) {
    const float2* pos = (const float2*)d_in[0];
    const float* W1  = (const float*)d_in[2];
    const float* b1  = (const float*)d_in[3];
    const float* W2  = (const float*)d_in[4];
    const float* b2  = (const float*)d_in[5];
    const float* W3  = (const float*)d_in[6];
    const float* b3  = (const float*)d_in[7];
    const float* Wl1 = (const float*)d_in[8];
    const float* bl1 = (const float*)d_in[9];
    const float* Wl2 = (const float*)d_in[10];
    const float* bl2 = (const float*)d_in[11];
    float* out = (float*)d_out;

    reorder_kernel<<<BGR, 256>>>(pos);                 // 0
    knn_kernel<<<BGR * 8, 256>>>();                    // 1
    convA_kernel<<<CONV_BLOCKS, 256>>>(W1, b1, W2);    // 2
    convB_kernel<<<CONV_BLOCKS, 256>>>(W2, b2, W3);    // 3  <- profiled
    convC_kernel<<<CONV_BLOCKS, 256>>>(W3, b3);        // 4
    head_kernel<<<1, 128>>>(Wl1, bl1, Wl2, bl2, out);  // 5
}

// round 15
// speedup vs baseline: 1.3301x; 1.0213x over previous
#include <cuda_runtime.h>
#include <cstdint>

#define NPTS 131072
#define BGR  64
#define NPG  2048
#define KNN  10
#define HD   64
#define CONV_BLOCKS (NPTS / 32)      // 4096
#define FULLMASK 0xffffffffu
#define PAIRNORM_EPS 1e-5f
#define ZPAD 65                      // s_z row stride
#define WPAD 65                      // sW row stride

// spatial grid for kNN
#define GDIM  64
#define NCELL (GDIM * GDIM)          // 4096
#define XMIN  (-5.0f)
#define CELL  0.15625f               // 10/64
#define INVCELL 6.4f

// ---------------------------------------------------------------------------
// Device scratch
// ---------------------------------------------------------------------------
__device__ float2 d_spos[NPTS];             // positions sorted by cell
__device__ int    d_sidx[NPTS];             // slot -> original local idx
__device__ int    d_slotof[NPTS];           // original local idx -> slot
__device__ int    d_cellstart[BGR * (NCELL + 1)];
__device__ int    d_knn[NPTS * KNN];        // neighbor GLOBAL SLOTS, row = slot
__device__ float  d_Ya[NPTS * HD];          // Yraw layer-2, slot-indexed
__device__ float  d_Yb[NPTS * HD];          // Yraw layer-3, slot-indexed
__device__ float  d_partT[65 * CONV_BLOCKS];// transposed partials [feature][block]
__device__ float  d_sum[65];                // per-feature totals
__device__ float  d_mean[HD];
__device__ float  d_scaleInv;
__device__ float  d_beff[HD];
__device__ int    d_pool[BGR * HD];         // pooled max (float bits, z>=0)
__device__ unsigned d_rc;                   // redstat ticket (self-resetting)

// ---------------------------------------------------------------------------
// init: zero the pool accumulator
// ---------------------------------------------------------------------------
__global__ void init_kernel() {
    int i = blockIdx.x * blockDim.x + threadIdx.x;
    if (i < BGR * HD) d_pool[i] = 0;
}

// ---------------------------------------------------------------------------
// reorder: per-graph counting sort by 64x64 cell id.
// Within-cell order nondeterministic (atomics) but kNN selection is
// order-independent (lexicographic (d2, original idx)) -> deterministic.
// ---------------------------------------------------------------------------
__global__ __launch_bounds__(256) void reorder_kernel(const float2* __restrict__ pos) {
    __shared__ int hist[NCELL];
    __shared__ unsigned short skey[NPG];
    __shared__ int scanbuf[256];
    int g = blockIdx.x;
    int tid = threadIdx.x;
    int base = g * NPG;

    for (int c = tid; c < NCELL; c += 256) hist[c] = 0;
    __syncthreads();

    for (int t = tid; t < NPG; t += 256) {
        float2 p = pos[base + t];
        int cx = (int)((p.x - XMIN) * INVCELL);
        int cy = (int)((p.y - XMIN) * INVCELL);
        cx = cx < 0 ? 0 : (cx > GDIM - 1 ? GDIM - 1 : cx);
        cy = cy < 0 ? 0 : (cy > GDIM - 1 ? GDIM - 1 : cy);
        unsigned key = (unsigned)(cy * GDIM + cx);
        skey[t] = (unsigned short)key;
        atomicAdd(&hist[key], 1);
    }
    __syncthreads();

    int cb = tid * 16;
    int loc[16];
    int tot = 0;
#pragma unroll
    for (int i = 0; i < 16; i++) { loc[i] = hist[cb + i]; tot += loc[i]; }
    scanbuf[tid] = tot;
    __syncthreads();
    for (int off = 1; off < 256; off <<= 1) {
        int add = 0;
        if (tid >= off) add = scanbuf[tid - off];
        __syncthreads();
        scanbuf[tid] += add;
        __syncthreads();
    }
    int run = scanbuf[tid] - tot;
#pragma unroll
    for (int i = 0; i < 16; i++) {
        hist[cb + i] = run;
        run += loc[i];
    }
    __syncthreads();

    int* cs = d_cellstart + g * (NCELL + 1);
    for (int c = tid; c < NCELL; c += 256) cs[c] = hist[c];
    if (tid == 0) cs[NCELL] = NPG;
    __syncthreads();

    for (int t = tid; t < NPG; t += 256) {
        int key = skey[t];
        int rank = atomicAdd(&hist[key], 1);
        d_spos[base + rank] = pos[base + t];
        d_sidx[base + rank] = t;
        d_slotof[base + t] = rank;
    }
}

// ---------------------------------------------------------------------------
// kNN (round-9 champion, 4x reproduced at 127us): single thread/query,
// warp-interleaved blocks, exact top-10 by lexicographic (d2, original idx).
// ---------------------------------------------------------------------------
#define INS2(da, db, ia, ib) { \
    if ((db < da) || (db == da && ib < ia)) { \
        float _t = da; da = db; db = _t; int _u = ia; ia = ib; ib = _u; } }

__global__ __launch_bounds__(256) void knn_kernel() {
    __shared__ float2 spos[NPG];
    __shared__ int    sidx[NPG];
    __shared__ int    scs[NCELL + 1];
    int g = blockIdx.x >> 3;
    int oct = blockIdx.x & 7;
    int base = g * NPG;
    int tid = threadIdx.x;
    int lane = tid & 31, wk = tid >> 5;

    for (int t = tid; t < NPG; t += 256) { spos[t] = d_spos[base + t]; sidx[t] = d_sidx[base + t]; }
    const int* gcs = d_cellstart + g * (NCELL + 1);
    for (int c = tid; c < NCELL + 1; c += 256) scs[c] = gcs[c];
    __syncthreads();

    int qw = wk * 8 + oct;
    int r = qw * 32 + lane;
    float2 q = spos[r];

    int cx = (int)((q.x - XMIN) * INVCELL);
    int cy = (int)((q.y - XMIN) * INVCELL);
    cx = cx < 0 ? 0 : (cx > GDIM - 1 ? GDIM - 1 : cx);
    cy = cy < 0 ? 0 : (cy > GDIM - 1 ? GDIM - 1 : cy);

    const float INF = __int_as_float(0x7f800000);
    float s0 = INF, s1 = INF, s2 = INF, s3 = INF, s4 = INF;
    float s5 = INF, s6 = INF, s7 = INF, s8 = INF, s9 = INF;
    int n0 = 0x7fffffff, n1 = n0, n2 = n0, n3 = n0, n4 = n0;
    int n5 = n0, n6 = n0, n7 = n0, n8 = n0, n9 = n0;

#define SCANRANGE(P0, P1) { \
    for (int _p = (P0); _p < (P1); _p++) { \
        float2 cp = spos[_p]; \
        float dx = q.x - cp.x; \
        float dy = q.y - cp.y; \
        float d2 = __fadd_rn(__fmul_rn(dx, dx), __fmul_rn(dy, dy)); \
        if (d2 <= s9 && _p != r) { \
            int oi = sidx[_p]; \
            if (d2 < s9 || oi < n9) { \
                s9 = d2; n9 = oi; \
                INS2(s8, s9, n8, n9); INS2(s7, s8, n7, n8); INS2(s6, s7, n6, n7); \
                INS2(s5, s6, n5, n6); INS2(s4, s5, n4, n5); INS2(s3, s4, n3, n4); \
                INS2(s2, s3, n2, n3); INS2(s1, s2, n1, n2); INS2(s0, s1, n0, n1); \
            } } } }

    for (int R = 0; R < GDIM; R++) {
        if (R >= 1) {
            float lox = XMIN + (float)(cx - R + 1) * CELL;
            float hix = XMIN + (float)(cx + R) * CELL;
            float loy = XMIN + (float)(cy - R + 1) * CELL;
            float hiy = XMIN + (float)(cy + R) * CELL;
            float bnd = fminf(fminf(q.x - lox, hix - q.x), fminf(q.y - loy, hiy - q.y));
            if (bnd > 0.f && bnd * bnd * 0.9999f > s9) break;
        }
        if (R == 0) {
            int c = cy * GDIM + cx;
            SCANRANGE(scs[c], scs[c + 1]);
        } else {
            int x0 = cx - R < 0 ? 0 : cx - R;
            int x1 = cx + R > GDIM - 1 ? GDIM - 1 : cx + R;
            if (cy - R >= 0) {
                int c = (cy - R) * GDIM;
                SCANRANGE(scs[c + x0], scs[c + x1 + 1]);
            }
            if (cy + R <= GDIM - 1) {
                int c = (cy + R) * GDIM;
                SCANRANGE(scs[c + x0], scs[c + x1 + 1]);
            }
            int y0 = cy - R + 1 < 0 ? 0 : cy - R + 1;
            int y1 = cy + R - 1 > GDIM - 1 ? GDIM - 1 : cy + R - 1;
            if (cx - R >= 0) {
                for (int yy = y0; yy <= y1; yy++) {
                    int c = yy * GDIM + cx - R;
                    SCANRANGE(scs[c], scs[c + 1]);
                }
            }
            if (cx + R <= GDIM - 1) {
                for (int yy = y0; yy <= y1; yy++) {
                    int c = yy * GDIM + cx + R;
                    SCANRANGE(scs[c], scs[c + 1]);
                }
            }
        }
    }

    const int* so = d_slotof + base;
    int* op = d_knn + (base + r) * KNN;
    op[0] = base + so[n0]; op[1] = base + so[n1]; op[2] = base + so[n2];
    op[3] = base + so[n3]; op[4] = base + so[n4]; op[5] = base + so[n5];
    op[6] = base + so[n6]; op[7] = base + so[n7]; op[8] = base + so[n8];
    op[9] = base + so[n9];
}

// ---------------------------------------------------------------------------
// block stats -> TRANSPOSED partials d_partT[feature][block]
// ---------------------------------------------------------------------------
__device__ __forceinline__ void block_stats(const float* s_z, float* s_red, int blockId) {
    int tid = threadIdx.x;
    if (tid < HD) {
        float s = 0.f, sq = 0.f;
#pragma unroll
        for (int r = 0; r < 32; r++) {
            float v = s_z[r * ZPAD + tid];
            s += v;
            sq = fmaf(v, v, sq);
        }
        d_partT[tid * CONV_BLOCKS + blockId] = s;
        s_red[tid] = sq;
    }
    __syncthreads();
    if (tid < 32) {
        float v = s_red[tid] + s_red[tid + 32];
#pragma unroll
        for (int off = 16; off > 0; off >>= 1)
            v += __shfl_down_sync(FULLMASK, v, off);
        if (tid == 0) d_partT[64 * CONV_BLOCKS + blockId] = v;
    }
}

// ---------------------------------------------------------------------------
// redstat: 65 blocks, coalesced column reduce; last block folds mean/inv/beff
// ---------------------------------------------------------------------------
__global__ __launch_bounds__(256) void redstat_kernel(const float* __restrict__ Wnext,
                                                      const float* __restrict__ bnext) {
    __shared__ float sred[256];
    __shared__ float smean[64];
    __shared__ int   s_last;
    int f = blockIdx.x;
    int tid = threadIdx.x;

    const float* col = d_partT + f * CONV_BLOCKS;
    float s = 0.f;
#pragma unroll
    for (int k = 0; k < CONV_BLOCKS / 256; k++) s += col[tid + k * 256];
    sred[tid] = s;
    __syncthreads();
    if (tid < 128) sred[tid] += sred[tid + 128];
    __syncthreads();
    if (tid < 64) sred[tid] += sred[tid + 64];
    __syncthreads();
    if (tid < 32) {
        float v = sred[tid] + sred[tid + 32];
#pragma unroll
        for (int off = 16; off > 0; off >>= 1)
            v += __shfl_down_sync(FULLMASK, v, off);
        if (tid == 0) d_sum[f] = v;
    }
    __threadfence();
    if (tid == 0) {
        unsigned t = atomicAdd(&d_rc, 1u);
        s_last = (t == 64u);
    }
    __syncthreads();
    if (!s_last) return;

    if (tid < 64) {
        float mean = d_sum[tid] * (1.0f / (float)NPTS);
        smean[tid] = mean;
        d_mean[tid] = mean;
    }
    __syncthreads();
    if (tid == 0) {
        float sq = d_sum[64];
        float ms = 0.f;
#pragma unroll 4
        for (int k = 0; k < 64; k++) ms = fmaf(smean[k], smean[k], ms);
        float denom = sq * (1.0f / (float)NPTS) - ms;
        d_scaleInv = 1.0f / sqrtf(PAIRNORM_EPS + denom);
        d_rc = 0;
    }
    __syncthreads();
    if (Wnext != nullptr && tid < 64) {
        float inv = d_scaleInv;
        float acc = 0.f;
#pragma unroll 4
        for (int k = 0; k < 64; k++) acc = fmaf(smean[k], Wnext[k * HD + tid], acc);
        d_beff[tid] = bnext[tid] - inv * acc;
    }
}

// ---------------------------------------------------------------------------
// split-tf32 mma epilogue (validated: rel_err 1.1e-6):
// C += Ahi*Bhi + Ahi*Blo + Alo*Bhi
// ---------------------------------------------------------------------------
__device__ __forceinline__ uint32_t f2tf32(float x) {
    uint32_t r;
    asm("cvt.rna.tf32.f32 %0, %1;" : "=r"(r) : "f"(x));
    return r;
}

__device__ __forceinline__ void mma_tf32(float* c, uint32_t a0, uint32_t a1,
                                         uint32_t a2, uint32_t a3,
                                         uint32_t b0, uint32_t b1) {
    asm volatile(
        "mma.sync.aligned.m16n8k8.row.col.f32.tf32.tf32.f32 "
        "{%0,%1,%2,%3}, {%4,%5,%6,%7}, {%8,%9}, {%0,%1,%2,%3};"
        : "+f"(c[0]), "+f"(c[1]), "+f"(c[2]), "+f"(c[3])
        : "r"(a0), "r"(a1), "r"(a2), "r"(a3), "r"(b0), "r"(b1));
}

__device__ __forceinline__ void epilogue_mma(const float* s_z,
                                             const uint32_t* sWhi,
                                             const uint32_t* sWlo,
                                             float* Yout, int nodebase) {
    int lane = threadIdx.x & 31;
    int w = threadIdx.x >> 5;
    int rt = w & 1;
    int nt0 = (w >> 1) * 2;
    int grp = lane >> 2;
    int idx = lane & 3;
    float c0[4] = {0.f, 0.f, 0.f, 0.f};
    float c1[4] = {0.f, 0.f, 0.f, 0.f};

#pragma unroll
    for (int ks = 0; ks < 8; ks++) {
        int k0 = ks * 8;
        int ar = rt * 16 + grp;
        float z0 = s_z[ar * ZPAD + k0 + idx];
        float z1 = s_z[(ar + 8) * ZPAD + k0 + idx];
        float z2 = s_z[ar * ZPAD + k0 + idx + 4];
        float z3 = s_z[(ar + 8) * ZPAD + k0 + idx + 4];
        uint32_t h0 = f2tf32(z0), h1 = f2tf32(z1), h2 = f2tf32(z2), h3 = f2tf32(z3);
        uint32_t l0 = f2tf32(z0 - __uint_as_float(h0));
        uint32_t l1 = f2tf32(z1 - __uint_as_float(h1));
        uint32_t l2 = f2tf32(z2 - __uint_as_float(h2));
        uint32_t l3 = f2tf32(z3 - __uint_as_float(h3));

        int nA = nt0 * 8 + grp;
        uint32_t bh0 = sWhi[(k0 + idx) * WPAD + nA];
        uint32_t bh1 = sWhi[(k0 + idx + 4) * WPAD + nA];
        uint32_t bl0 = sWlo[(k0 + idx) * WPAD + nA];
        uint32_t bl1 = sWlo[(k0 + idx + 4) * WPAD + nA];
        mma_tf32(c0, h0, h1, h2, h3, bh0, bh1);
        mma_tf32(c0, h0, h1, h2, h3, bl0, bl1);
        mma_tf32(c0, l0, l1, l2, l3, bh0, bh1);

        int nB = (nt0 + 1) * 8 + grp;
        uint32_t ch0 = sWhi[(k0 + idx) * WPAD + nB];
        uint32_t ch1 = sWhi[(k0 + idx + 4) * WPAD + nB];
        uint32_t cl0 = sWlo[(k0 + idx) * WPAD + nB];
        uint32_t cl1 = sWlo[(k0 + idx + 4) * WPAD + nB];
        mma_tf32(c1, h0, h1, h2, h3, ch0, ch1);
        mma_tf32(c1, h0, h1, h2, h3, cl0, cl1);
        mma_tf32(c1, l0, l1, l2, l3, ch0, ch1);
    }

    int row = rt * 16 + grp;
    int colA = nt0 * 8 + idx * 2;
    int colB = (nt0 + 1) * 8 + idx * 2;
    *(float2*)(Yout + (nodebase + row) * HD + colA)       = make_float2(c0[0], c0[1]);
    *(float2*)(Yout + (nodebase + row + 8) * HD + colA)   = make_float2(c0[2], c0[3]);
    *(float2*)(Yout + (nodebase + row) * HD + colB)       = make_float2(c1[0], c1[1]);
    *(float2*)(Yout + (nodebase + row + 8) * HD + colB)   = make_float2(c1[2], c1[3]);
}

__device__ __forceinline__ void load_W_split(uint32_t* sWhi, uint32_t* sWlo,
                                             const float* W) {
    int tid = threadIdx.x;
    for (int i = tid; i < HD * HD; i += 256) {
        float w = W[i];
        uint32_t hi = f2tf32(w);
        uint32_t lo = f2tf32(w - __uint_as_float(hi));
        int o = (i >> 6) * WPAD + (i & 63);
        sWhi[o] = hi;
        sWlo[o] = lo;
    }
}

// ---------------------------------------------------------------------------
// convA (layer 1): msg = rel @ W1 + b1, max + relu; stats -> d_partT;
//   split-tf32 epilogue Yraw2 = z @ W2x -> d_Ya
// ---------------------------------------------------------------------------
__global__ __launch_bounds__(256) void convA_kernel(const float* __restrict__ W1,
                                                    const float* __restrict__ b1,
                                                    const float* __restrict__ W2) {
    __shared__ float    s_z[32 * ZPAD];
    __shared__ uint32_t sWhi[HD * WPAD];
    __shared__ uint32_t sWlo[HD * WPAD];
    __shared__ float2   s_pj[8][2 * KNN];
    __shared__ float    s_red[64];
    int tid = threadIdx.x, lane = tid & 31, wid = tid >> 5;
    int f0 = lane * 2, f1 = f0 + 1;
    float wx0 = W1[f0],      wx1 = W1[f1];
    float wy0 = W1[HD + f0], wy1 = W1[HD + f1];
    float bb0 = b1[f0],      bb1 = b1[f1];
    int nodebase = blockIdx.x * 32;

    load_W_split(sWhi, sWlo, W2);

    for (int half = 0; half < 2; half++) {
        int nb = nodebase + wid * 4 + half * 2;
        if (lane < 2 * KNN) {
            int nd = nb + (lane >= KNN ? 1 : 0);
            int e = lane >= KNN ? lane - KNN : lane;
            int jj = d_knn[nd * KNN + e];
            s_pj[wid][lane] = d_spos[jj];
        }
        __syncwarp();
#pragma unroll
        for (int it = 0; it < 2; it++) {
            int node = nb + it;
            float2 pi = d_spos[node];
            float m0 = bb0, m1 = bb1;            // self edge rel=0
#pragma unroll
            for (int e = 0; e < KNN; e++) {
                float2 pj = s_pj[wid][it * KNN + e];
                float rx = pj.x - pi.x, ry = pj.y - pi.y;
                m0 = fmaxf(m0, fmaf(rx, wx0, fmaf(ry, wy0, bb0)));
                m1 = fmaxf(m1, fmaf(rx, wx1, fmaf(ry, wy1, bb1)));
            }
            int r = wid * 4 + half * 2 + it;
            s_z[r * ZPAD + f0] = fmaxf(m0, 0.f);
            s_z[r * ZPAD + f1] = fmaxf(m1, 0.f);
        }
        __syncwarp();
    }
    __syncthreads();
    block_stats(s_z, s_red, blockIdx.x);
    __syncthreads();
    epilogue_mma(s_z, sWhi, sWlo, d_Ya, nodebase);
}

// ---------------------------------------------------------------------------
// convB (layer 2): 2-node edge staging (20 loads in flight), gather d_Ya;
//   stats -> d_partT; split-tf32 epilogue (W3) -> d_Yb
// ---------------------------------------------------------------------------
__global__ __launch_bounds__(256) void convB_kernel(const float* __restrict__ W2,
                                                    const float* __restrict__ W3) {
    __shared__ float    s_z[32 * ZPAD];
    __shared__ uint32_t sWhi[HD * WPAD];
    __shared__ uint32_t sWlo[HD * WPAD];
    __shared__ float2   s_pj[8][2 * KNN];
    __shared__ int      s_j[8][2 * KNN];
    __shared__ float    s_red[64];
    int tid = threadIdx.x, lane = tid & 31, wid = tid >> 5;
    int f0 = lane * 2, f1 = f0 + 1;
    float wx0 = W2[64 * HD + f0], wx1 = W2[64 * HD + f1];
    float wy0 = W2[65 * HD + f0], wy1 = W2[65 * HD + f1];
    float be0 = d_beff[f0], be1 = d_beff[f1];
    float inv = d_scaleInv;
    int nodebase = blockIdx.x * 32;

    load_W_split(sWhi, sWlo, W3);

    for (int half = 0; half < 2; half++) {
        int nb = nodebase + wid * 4 + half * 2;
        if (lane < 2 * KNN) {
            int nd = nb + (lane >= KNN ? 1 : 0);
            int e = lane >= KNN ? lane - KNN : lane;
            int jj = d_knn[nd * KNN + e];
            s_pj[wid][lane] = d_spos[jj];
            s_j[wid][lane] = jj;
        }
        __syncwarp();
#pragma unroll
        for (int it = 0; it < 2; it++) {
            int node = nb + it;
            float2 pi = d_spos[node];
            float2 ys = *(const float2*)(d_Ya + node * HD + f0);
            float m0 = fmaf(inv, ys.x, be0), m1 = fmaf(inv, ys.y, be1);
#pragma unroll
            for (int e = 0; e < KNN; e++) {
                float2 pj = s_pj[wid][it * KNN + e];
                int j = s_j[wid][it * KNN + e];
                float rx = pj.x - pi.x, ry = pj.y - pi.y;
                float2 yv = *(const float2*)(d_Ya + j * HD + f0);
                m0 = fmaxf(m0, fmaf(inv, yv.x, fmaf(rx, wx0, fmaf(ry, wy0, be0))));
                m1 = fmaxf(m1, fmaf(inv, yv.y, fmaf(rx, wx1, fmaf(ry, wy1, be1))));
            }
            int r = wid * 4 + half * 2 + it;
            s_z[r * ZPAD + f0] = fmaxf(m0, 0.f);
            s_z[r * ZPAD + f1] = fmaxf(m1, 0.f);
        }
        __syncwarp();
    }
    __syncthreads();
    block_stats(s_z, s_red, blockIdx.x);
    __syncthreads();
    epilogue_mma(s_z, sWhi, sWlo, d_Yb, nodebase);
}

// ---------------------------------------------------------------------------
// convC (layer 3): 2-node staging, gather d_Yb; stats; per-graph max pool
// ---------------------------------------------------------------------------
__global__ __launch_bounds__(256) void convC_kernel(const float* __restrict__ W3) {
    __shared__ float  s_z[32 * ZPAD];
    __shared__ float2 s_pj[8][2 * KNN];
    __shared__ int    s_j[8][2 * KNN];
    __shared__ float  s_red[64];
    int tid = threadIdx.x, lane = tid & 31, wid = tid >> 5;
    int f0 = lane * 2, f1 = f0 + 1;
    float wx0 = W3[64 * HD + f0], wx1 = W3[64 * HD + f1];
    float wy0 = W3[65 * HD + f0], wy1 = W3[65 * HD + f1];
    float be0 = d_beff[f0], be1 = d_beff[f1];
    float inv = d_scaleInv;
    int nodebase = blockIdx.x * 32;

    for (int half = 0; half < 2; half++) {
        int nb = nodebase + wid * 4 + half * 2;
        if (lane < 2 * KNN) {
            int nd = nb + (lane >= KNN ? 1 : 0);
            int e = lane >= KNN ? lane - KNN : lane;
            int jj = d_knn[nd * KNN + e];
            s_pj[wid][lane] = d_spos[jj];
            s_j[wid][lane] = jj;
        }
        __syncwarp();
#pragma unroll
        for (int it = 0; it < 2; it++) {
            int node = nb + it;
            float2 pi = d_spos[node];
            float2 ys = *(const float2*)(d_Yb + node * HD + f0);
            float m0 = fmaf(inv, ys.x, be0), m1 = fmaf(inv, ys.y, be1);
#pragma unroll
            for (int e = 0; e < KNN; e++) {
                float2 pj = s_pj[wid][it * KNN + e];
                int j = s_j[wid][it * KNN + e];
                float rx = pj.x - pi.x, ry = pj.y - pi.y;
                float2 yv = *(const float2*)(d_Yb + j * HD + f0);
                m0 = fmaxf(m0, fmaf(inv, yv.x, fmaf(rx, wx0, fmaf(ry, wy0, be0))));
                m1 = fmaxf(m1, fmaf(inv, yv.y, fmaf(rx, wx1, fmaf(ry, wy1, be1))));
            }
            int r = wid * 4 + half * 2 + it;
            s_z[r * ZPAD + f0] = fmaxf(m0, 0.f);
            s_z[r * ZPAD + f1] = fmaxf(m1, 0.f);
        }
        __syncwarp();
    }
    __syncthreads();
    block_stats(s_z, s_red, blockIdx.x);
    if (tid < HD) {
        float m = s_z[tid];
#pragma unroll
        for (int r = 1; r < 32; r++) m = fmaxf(m, s_z[r * ZPAD + tid]);
        int g = blockIdx.x >> 6;
        atomicMax(&d_pool[g * HD + tid], __float_as_int(m));
    }
}

// ---------------------------------------------------------------------------
// head: normalize pooled max on the fly; MLP -> out[64,2]
// ---------------------------------------------------------------------------
__global__ __launch_bounds__(128) void head_kernel(const float* __restrict__ Wl1,
                                                   const float* __restrict__ bl1,
                                                   const float* __restrict__ Wl2,
                                                   const float* __restrict__ bl2,
                                                   float* __restrict__ out) {
    __shared__ float t1[BGR * HD];
    __shared__ float sW[HD * HD];
    __shared__ float s_mean[64];
    int tid = threadIdx.x;
    float inv = d_scaleInv;

    if (tid < HD) s_mean[tid] = d_mean[tid];
    const float4* W4 = (const float4*)Wl1;
    float4* sW4 = (float4*)sW;
    for (int i = tid; i < HD * HD / 4; i += 128) sW4[i] = W4[i];
    __syncthreads();

    int g = tid >> 1, half = tid & 1;
    float acc[32];
#pragma unroll
    for (int c = 0; c < 32; c++) acc[c] = bl1[half * 32 + c];
    for (int k = 0; k < HD; k++) {
        float h = (__int_as_float(d_pool[g * HD + k]) - s_mean[k]) * inv;
        const float* wrow = sW + k * HD + half * 32;
#pragma unroll
        for (int c = 0; c < 32; c++) acc[c] = fmaf(h, wrow[c], acc[c]);
    }
#pragma unroll
    for (int c = 0; c < 32; c++) t1[g * HD + half * 32 + c] = fmaxf(acc[c], 0.f);
    __syncthreads();

    int gg = tid >> 1, o = tid & 1;
    float s = bl2[o];
    for (int k = 0; k < HD; k++) s = fmaf(t1[gg * HD + k], Wl2[k * 2 + o], s);
    out[gg * 2 + o] = s;
}

// ---------------------------------------------------------------------------
// launch — capture index 3 = convA (split-tf32 epilogue profile)
// ---------------------------------------------------------------------------
extern "C" void kernel_launch(void* const* d_in, const int* in_sizes, int n_in,
                              void* d_out, int out_size) {
    const float2* pos = (const float2*)d_in[0];
    const float* W1  = (const float*)d_in[2];
    const float* b1  = (const float*)d_in[3];
    const float* W2  = (const float*)d_in[4];
    const float* b2  = (const float*)d_in[5];
    const float* W3  = (const float*)d_in[6];
    const float* b3  = (const float*)d_in[7];
    const float* Wl1 = (const float*)d_in[8];
    const float* bl1 = (const float*)d_in[9];
    const float* Wl2 = (const float*)d_in[10];
    const float* bl2 = (const float*)d_in[11];
    float* out = (float*)d_out;

    init_kernel<<<16, 256>>>();                        // 0
    reorder_kernel<<<BGR, 256>>>(pos);                 // 1
    knn_kernel<<<BGR * 8, 256>>>();                    // 2
    convA_kernel<<<CONV_BLOCKS, 256>>>(W1, b1, W2);    // 3  <- profiled
    redstat_kernel<<<65, 256>>>(W2, b2);               // 4
    convB_kernel<<<CONV_BLOCKS, 256>>>(W2, W3);        // 5
    redstat_kernel<<<65, 256>>>(W3, b3);               // 6
    convC_kernel<<<CONV_BLOCKS, 256>>>(W3);            // 7
    redstat_kernel<<<65, 256>>>(nullptr, nullptr);     // 8
    head_kernel<<<1, 128>>>(Wl1, bl1, Wl2, bl2, out);  // 9
}

// round 16
// speedup vs baseline: 1.5139x; 1.1382x over previous
#include <cuda_runtime.h>
#include <cstdint>

#define NPTS 131072
#define BGR  64
#define NPG  2048
#define KNN  10
#define HD   64
#define CONV_BLOCKS (NPTS / 32)      // 4096
#define FULLMASK 0xffffffffu
#define PAIRNORM_EPS 1e-5f
#define ZPAD 65                      // s_z row stride (conflict-free scalar)

// spatial grid for kNN
#define GDIM  64
#define NCELL (GDIM * GDIM)          // 4096
#define XMIN  (-5.0f)
#define CELL  0.15625f               // 10/64
#define INVCELL 6.4f

// ---------------------------------------------------------------------------
// Device scratch
// ---------------------------------------------------------------------------
__device__ float2 d_spos[NPTS];             // positions sorted by cell
__device__ int    d_sidx[NPTS];             // slot -> original local idx
__device__ int    d_slotof[NPTS];           // original local idx -> slot
__device__ int    d_cellstart[BGR * (NCELL + 1)];
__device__ int    d_knn[NPTS * KNN];        // neighbor GLOBAL SLOTS, row = slot
__device__ float  d_Ya[NPTS * HD];          // Yraw layer-2, slot-indexed
__device__ float  d_Yb[NPTS * HD];          // Yraw layer-3, slot-indexed
__device__ float  d_partT[65 * CONV_BLOCKS];// transposed partials [feature][block]
__device__ float  d_sum[65];                // per-feature totals
__device__ float  d_mean[HD];
__device__ float  d_scaleInv;
__device__ float  d_beff[HD];
__device__ int    d_pool[BGR * HD];         // pooled max (float bits, z>=0)
__device__ unsigned d_rc;                   // redstat ticket (self-resetting)

// ---------------------------------------------------------------------------
// init: zero the pool accumulator
// ---------------------------------------------------------------------------
__global__ void init_kernel() {
    int i = blockIdx.x * blockDim.x + threadIdx.x;
    if (i < BGR * HD) d_pool[i] = 0;
}

// ---------------------------------------------------------------------------
// reorder: per-graph counting sort by 64x64 cell id.
// Within-cell order nondeterministic (atomics) but kNN selection is
// order-independent (lexicographic (d2, original idx)) -> deterministic.
// ---------------------------------------------------------------------------
__global__ __launch_bounds__(256) void reorder_kernel(const float2* __restrict__ pos) {
    __shared__ int hist[NCELL];
    __shared__ unsigned short skey[NPG];
    __shared__ int scanbuf[256];
    int g = blockIdx.x;
    int tid = threadIdx.x;
    int base = g * NPG;

    for (int c = tid; c < NCELL; c += 256) hist[c] = 0;
    __syncthreads();

    for (int t = tid; t < NPG; t += 256) {
        float2 p = pos[base + t];
        int cx = (int)((p.x - XMIN) * INVCELL);
        int cy = (int)((p.y - XMIN) * INVCELL);
        cx = cx < 0 ? 0 : (cx > GDIM - 1 ? GDIM - 1 : cx);
        cy = cy < 0 ? 0 : (cy > GDIM - 1 ? GDIM - 1 : cy);
        unsigned key = (unsigned)(cy * GDIM + cx);
        skey[t] = (unsigned short)key;
        atomicAdd(&hist[key], 1);
    }
    __syncthreads();

    int cb = tid * 16;
    int loc[16];
    int tot = 0;
#pragma unroll
    for (int i = 0; i < 16; i++) { loc[i] = hist[cb + i]; tot += loc[i]; }
    scanbuf[tid] = tot;
    __syncthreads();
    for (int off = 1; off < 256; off <<= 1) {
        int add = 0;
        if (tid >= off) add = scanbuf[tid - off];
        __syncthreads();
        scanbuf[tid] += add;
        __syncthreads();
    }
    int run = scanbuf[tid] - tot;
#pragma unroll
    for (int i = 0; i < 16; i++) {
        hist[cb + i] = run;
        run += loc[i];
    }
    __syncthreads();

    int* cs = d_cellstart + g * (NCELL + 1);
    for (int c = tid; c < NCELL; c += 256) cs[c] = hist[c];
    if (tid == 0) cs[NCELL] = NPG;
    __syncthreads();

    for (int t = tid; t < NPG; t += 256) {
        int key = skey[t];
        int rank = atomicAdd(&hist[key], 1);
        d_spos[base + rank] = pos[base + t];
        d_sidx[base + rank] = t;
        d_slotof[base + t] = rank;
    }
}

// ---------------------------------------------------------------------------
// kNN (round-9 champion, 5x reproduced at 127us): single thread/query,
// warp-interleaved blocks, exact top-10 by lexicographic (d2, original idx).
// ---------------------------------------------------------------------------
#define INS2(da, db, ia, ib) { \
    if ((db < da) || (db == da && ib < ia)) { \
        float _t = da; da = db; db = _t; int _u = ia; ia = ib; ib = _u; } }

__global__ __launch_bounds__(256) void knn_kernel() {
    __shared__ float2 spos[NPG];
    __shared__ int    sidx[NPG];
    __shared__ int    scs[NCELL + 1];
    int g = blockIdx.x >> 3;
    int oct = blockIdx.x & 7;
    int base = g * NPG;
    int tid = threadIdx.x;
    int lane = tid & 31, wk = tid >> 5;

    for (int t = tid; t < NPG; t += 256) { spos[t] = d_spos[base + t]; sidx[t] = d_sidx[base + t]; }
    const int* gcs = d_cellstart + g * (NCELL + 1);
    for (int c = tid; c < NCELL + 1; c += 256) scs[c] = gcs[c];
    __syncthreads();

    int qw = wk * 8 + oct;
    int r = qw * 32 + lane;
    float2 q = spos[r];

    int cx = (int)((q.x - XMIN) * INVCELL);
    int cy = (int)((q.y - XMIN) * INVCELL);
    cx = cx < 0 ? 0 : (cx > GDIM - 1 ? GDIM - 1 : cx);
    cy = cy < 0 ? 0 : (cy > GDIM - 1 ? GDIM - 1 : cy);

    const float INF = __int_as_float(0x7f800000);
    float s0 = INF, s1 = INF, s2 = INF, s3 = INF, s4 = INF;
    float s5 = INF, s6 = INF, s7 = INF, s8 = INF, s9 = INF;
    int n0 = 0x7fffffff, n1 = n0, n2 = n0, n3 = n0, n4 = n0;
    int n5 = n0, n6 = n0, n7 = n0, n8 = n0, n9 = n0;

#define SCANRANGE(P0, P1) { \
    for (int _p = (P0); _p < (P1); _p++) { \
        float2 cp = spos[_p]; \
        float dx = q.x - cp.x; \
        float dy = q.y - cp.y; \
        float d2 = __fadd_rn(__fmul_rn(dx, dx), __fmul_rn(dy, dy)); \
        if (d2 <= s9 && _p != r) { \
            int oi = sidx[_p]; \
            if (d2 < s9 || oi < n9) { \
                s9 = d2; n9 = oi; \
                INS2(s8, s9, n8, n9); INS2(s7, s8, n7, n8); INS2(s6, s7, n6, n7); \
                INS2(s5, s6, n5, n6); INS2(s4, s5, n4, n5); INS2(s3, s4, n3, n4); \
                INS2(s2, s3, n2, n3); INS2(s1, s2, n1, n2); INS2(s0, s1, n0, n1); \
            } } } }

    for (int R = 0; R < GDIM; R++) {
        if (R >= 1) {
            float lox = XMIN + (float)(cx - R + 1) * CELL;
            float hix = XMIN + (float)(cx + R) * CELL;
            float loy = XMIN + (float)(cy - R + 1) * CELL;
            float hiy = XMIN + (float)(cy + R) * CELL;
            float bnd = fminf(fminf(q.x - lox, hix - q.x), fminf(q.y - loy, hiy - q.y));
            if (bnd > 0.f && bnd * bnd * 0.9999f > s9) break;
        }
        if (R == 0) {
            int c = cy * GDIM + cx;
            SCANRANGE(scs[c], scs[c + 1]);
        } else {
            int x0 = cx - R < 0 ? 0 : cx - R;
            int x1 = cx + R > GDIM - 1 ? GDIM - 1 : cx + R;
            if (cy - R >= 0) {
                int c = (cy - R) * GDIM;
                SCANRANGE(scs[c + x0], scs[c + x1 + 1]);
            }
            if (cy + R <= GDIM - 1) {
                int c = (cy + R) * GDIM;
                SCANRANGE(scs[c + x0], scs[c + x1 + 1]);
            }
            int y0 = cy - R + 1 < 0 ? 0 : cy - R + 1;
            int y1 = cy + R - 1 > GDIM - 1 ? GDIM - 1 : cy + R - 1;
            if (cx - R >= 0) {
                for (int yy = y0; yy <= y1; yy++) {
                    int c = yy * GDIM + cx - R;
                    SCANRANGE(scs[c], scs[c + 1]);
                }
            }
            if (cx + R <= GDIM - 1) {
                for (int yy = y0; yy <= y1; yy++) {
                    int c = yy * GDIM + cx + R;
                    SCANRANGE(scs[c], scs[c + 1]);
                }
            }
        }
    }

    const int* so = d_slotof + base;
    int* op = d_knn + (base + r) * KNN;
    op[0] = base + so[n0]; op[1] = base + so[n1]; op[2] = base + so[n2];
    op[3] = base + so[n3]; op[4] = base + so[n4]; op[5] = base + so[n5];
    op[6] = base + so[n6]; op[7] = base + so[n7]; op[8] = base + so[n8];
    op[9] = base + so[n9];
}

// ---------------------------------------------------------------------------
// block stats -> TRANSPOSED partials d_partT[feature][block]
// ---------------------------------------------------------------------------
__device__ __forceinline__ void block_stats(const float* s_z, float* s_red, int blockId) {
    int tid = threadIdx.x;
    if (tid < HD) {
        float s = 0.f, sq = 0.f;
#pragma unroll
        for (int r = 0; r < 32; r++) {
            float v = s_z[r * ZPAD + tid];
            s += v;
            sq = fmaf(v, v, sq);
        }
        d_partT[tid * CONV_BLOCKS + blockId] = s;
        s_red[tid] = sq;
    }
    __syncthreads();
    if (tid < 32) {
        float v = s_red[tid] + s_red[tid + 32];
#pragma unroll
        for (int off = 16; off > 0; off >>= 1)
            v += __shfl_down_sync(FULLMASK, v, off);
        if (tid == 0) d_partT[64 * CONV_BLOCKS + blockId] = v;
    }
}

// ---------------------------------------------------------------------------
// redstat: 65 blocks, coalesced column reduce; last block folds mean/inv/beff
// ---------------------------------------------------------------------------
__global__ __launch_bounds__(256) void redstat_kernel(const float* __restrict__ Wnext,
                                                      const float* __restrict__ bnext) {
    __shared__ float sred[256];
    __shared__ float smean[64];
    __shared__ int   s_last;
    int f = blockIdx.x;
    int tid = threadIdx.x;

    const float* col = d_partT + f * CONV_BLOCKS;
    float s = 0.f;
#pragma unroll
    for (int k = 0; k < CONV_BLOCKS / 256; k++) s += col[tid + k * 256];
    sred[tid] = s;
    __syncthreads();
    if (tid < 128) sred[tid] += sred[tid + 128];
    __syncthreads();
    if (tid < 64) sred[tid] += sred[tid + 64];
    __syncthreads();
    if (tid < 32) {
        float v = sred[tid] + sred[tid + 32];
#pragma unroll
        for (int off = 16; off > 0; off >>= 1)
            v += __shfl_down_sync(FULLMASK, v, off);
        if (tid == 0) d_sum[f] = v;
    }
    __threadfence();
    if (tid == 0) {
        unsigned t = atomicAdd(&d_rc, 1u);
        s_last = (t == 64u);
    }
    __syncthreads();
    if (!s_last) return;

    if (tid < 64) {
        float mean = d_sum[tid] * (1.0f / (float)NPTS);
        smean[tid] = mean;
        d_mean[tid] = mean;
    }
    __syncthreads();
    if (tid == 0) {
        float sq = d_sum[64];
        float ms = 0.f;
#pragma unroll 4
        for (int k = 0; k < 64; k++) ms = fmaf(smean[k], smean[k], ms);
        float denom = sq * (1.0f / (float)NPTS) - ms;
        d_scaleInv = 1.0f / sqrtf(PAIRNORM_EPS + denom);
        d_rc = 0;
    }
    __syncthreads();
    if (Wnext != nullptr && tid < 64) {
        float inv = d_scaleInv;
        float acc = 0.f;
#pragma unroll 4
        for (int k = 0; k < 64; k++) acc = fmaf(smean[k], Wnext[k * HD + tid], acc);
        d_beff[tid] = bnext[tid] - inv * acc;
    }
}

// ---------------------------------------------------------------------------
// epilogue GEMM (r9-proven, exact fp32): Yout[32x64] = s_z @ sW(64x64)
// thread: row = tid&31, colgroup = tid>>5 (8 cols each)
// ---------------------------------------------------------------------------
__device__ __forceinline__ void epilogue_gemm(const float* s_z, const float4* sW,
                                              float* Yout, int nodebase) {
    int tid = threadIdx.x;
    int row = tid & 31;
    int cg = tid >> 5;
    float4 a0 = make_float4(0.f, 0.f, 0.f, 0.f);
    float4 a1 = make_float4(0.f, 0.f, 0.f, 0.f);
    const float* zr = s_z + row * ZPAD;
#pragma unroll 4
    for (int k = 0; k < 64; k++) {
        float zk = zr[k];
        float4 w0 = sW[k * 16 + cg * 2];
        float4 w1 = sW[k * 16 + cg * 2 + 1];
        a0.x = fmaf(zk, w0.x, a0.x); a0.y = fmaf(zk, w0.y, a0.y);
        a0.z = fmaf(zk, w0.z, a0.z); a0.w = fmaf(zk, w0.w, a0.w);
        a1.x = fmaf(zk, w1.x, a1.x); a1.y = fmaf(zk, w1.y, a1.y);
        a1.z = fmaf(zk, w1.z, a1.z); a1.w = fmaf(zk, w1.w, a1.w);
    }
    float4* yo = (float4*)(Yout + (nodebase + row) * HD + cg * 8);
    yo[0] = a0;
    yo[1] = a1;
}

// ---------------------------------------------------------------------------
// convA (layer 1): 2-node edge staging; msg = rel @ W1 + b1, max + relu;
//   stats -> d_partT; FFMA epilogue Yraw2 = z @ W2x -> d_Ya
// ---------------------------------------------------------------------------
__global__ __launch_bounds__(256) void convA_kernel(const float* __restrict__ W1,
                                                    const float* __restrict__ b1,
                                                    const float* __restrict__ W2) {
    __shared__ float  s_z[32 * ZPAD];
    __shared__ float4 sW[1024];
    __shared__ float2 s_pj[8][2 * KNN];
    __shared__ float  s_red[64];
    int tid = threadIdx.x, lane = tid & 31, wid = tid >> 5;
    int f0 = lane * 2, f1 = f0 + 1;
    float wx0 = W1[f0],      wx1 = W1[f1];
    float wy0 = W1[HD + f0], wy1 = W1[HD + f1];
    float bb0 = b1[f0],      bb1 = b1[f1];
    int nodebase = blockIdx.x * 32;

    const float4* W2x4 = (const float4*)W2;
    for (int i = tid; i < 1024; i += 256) sW[i] = W2x4[i];

    for (int half = 0; half < 2; half++) {
        int nb = nodebase + wid * 4 + half * 2;
        if (lane < 2 * KNN) {
            int nd = nb + (lane >= KNN ? 1 : 0);
            int e = lane >= KNN ? lane - KNN : lane;
            int jj = d_knn[nd * KNN + e];
            s_pj[wid][lane] = d_spos[jj];
        }
        __syncwarp();
#pragma unroll
        for (int it = 0; it < 2; it++) {
            int node = nb + it;
            float2 pi = d_spos[node];
            float m0 = bb0, m1 = bb1;            // self edge rel=0
#pragma unroll
            for (int e = 0; e < KNN; e++) {
                float2 pj = s_pj[wid][it * KNN + e];
                float rx = pj.x - pi.x, ry = pj.y - pi.y;
                m0 = fmaxf(m0, fmaf(rx, wx0, fmaf(ry, wy0, bb0)));
                m1 = fmaxf(m1, fmaf(rx, wx1, fmaf(ry, wy1, bb1)));
            }
            int r = wid * 4 + half * 2 + it;
            s_z[r * ZPAD + f0] = fmaxf(m0, 0.f);
            s_z[r * ZPAD + f1] = fmaxf(m1, 0.f);
        }
        __syncwarp();
    }
    __syncthreads();
    block_stats(s_z, s_red, blockIdx.x);
    __syncthreads();
    epilogue_gemm(s_z, sW, d_Ya, nodebase);
}

// ---------------------------------------------------------------------------
// convB (layer 2): 2-node edge staging (20 gathers in flight), gather d_Ya;
//   stats -> d_partT; FFMA epilogue (W3) -> d_Yb
// ---------------------------------------------------------------------------
__global__ __launch_bounds__(256) void convB_kernel(const float* __restrict__ W2,
                                                    const float* __restrict__ W3) {
    __shared__ float  s_z[32 * ZPAD];
    __shared__ float4 sW[1024];
    __shared__ float2 s_pj[8][2 * KNN];
    __shared__ int    s_j[8][2 * KNN];
    __shared__ float  s_red[64];
    int tid = threadIdx.x, lane = tid & 31, wid = tid >> 5;
    int f0 = lane * 2, f1 = f0 + 1;
    float wx0 = W2[64 * HD + f0], wx1 = W2[64 * HD + f1];
    float wy0 = W2[65 * HD + f0], wy1 = W2[65 * HD + f1];
    float be0 = d_beff[f0], be1 = d_beff[f1];
    float inv = d_scaleInv;
    int nodebase = blockIdx.x * 32;

    const float4* W3x4 = (const float4*)W3;
    for (int i = tid; i < 1024; i += 256) sW[i] = W3x4[i];

    for (int half = 0; half < 2; half++) {
        int nb = nodebase + wid * 4 + half * 2;
        if (lane < 2 * KNN) {
            int nd = nb + (lane >= KNN ? 1 : 0);
            int e = lane >= KNN ? lane - KNN : lane;
            int jj = d_knn[nd * KNN + e];
            s_pj[wid][lane] = d_spos[jj];
            s_j[wid][lane] = jj;
        }
        __syncwarp();
#pragma unroll
        for (int it = 0; it < 2; it++) {
            int node = nb + it;
            float2 pi = d_spos[node];
            float2 ys = *(const float2*)(d_Ya + node * HD + f0);
            float m0 = fmaf(inv, ys.x, be0), m1 = fmaf(inv, ys.y, be1);
#pragma unroll
            for (int e = 0; e < KNN; e++) {
                float2 pj = s_pj[wid][it * KNN + e];
                int j = s_j[wid][it * KNN + e];
                float rx = pj.x - pi.x, ry = pj.y - pi.y;
                float2 yv = *(const float2*)(d_Ya + j * HD + f0);
                m0 = fmaxf(m0, fmaf(inv, yv.x, fmaf(rx, wx0, fmaf(ry, wy0, be0))));
                m1 = fmaxf(m1, fmaf(inv, yv.y, fmaf(rx, wx1, fmaf(ry, wy1, be1))));
            }
            int r = wid * 4 + half * 2 + it;
            s_z[r * ZPAD + f0] = fmaxf(m0, 0.f);
            s_z[r * ZPAD + f1] = fmaxf(m1, 0.f);
        }
        __syncwarp();
    }
    __syncthreads();
    block_stats(s_z, s_red, blockIdx.x);
    __syncthreads();
    epilogue_gemm(s_z, sW, d_Yb, nodebase);
}

// ---------------------------------------------------------------------------
// convC (layer 3): 2-node staging, gather d_Yb; stats; per-graph max pool
// ---------------------------------------------------------------------------
__global__ __launch_bounds__(256) void convC_kernel(const float* __restrict__ W3) {
    __shared__ float  s_z[32 * ZPAD];
    __shared__ float2 s_pj[8][2 * KNN];
    __shared__ int    s_j[8][2 * KNN];
    __shared__ float  s_red[64];
    int tid = threadIdx.x, lane = tid & 31, wid = tid >> 5;
    int f0 = lane * 2, f1 = f0 + 1;
    float wx0 = W3[64 * HD + f0], wx1 = W3[64 * HD + f1];
    float wy0 = W3[65 * HD + f0], wy1 = W3[65 * HD + f1];
    float be0 = d_beff[f0], be1 = d_beff[f1];
    float inv = d_scaleInv;
    int nodebase = blockIdx.x * 32;

    for (int half = 0; half < 2; half++) {
        int nb = nodebase + wid * 4 + half * 2;
        if (lane < 2 * KNN) {
            int nd = nb + (lane >= KNN ? 1 : 0);
            int e = lane >= KNN ? lane - KNN : lane;
            int jj = d_knn[nd * KNN + e];
            s_pj[wid][lane] = d_spos[jj];
            s_j[wid][lane] = jj;
        }
        __syncwarp();
#pragma unroll
        for (int it = 0; it < 2; it++) {
            int node = nb + it;
            float2 pi = d_spos[node];
            float2 ys = *(const float2*)(d_Yb + node * HD + f0);
            float m0 = fmaf(inv, ys.x, be0), m1 = fmaf(inv, ys.y, be1);
#pragma unroll
            for (int e = 0; e < KNN; e++) {
                float2 pj = s_pj[wid][it * KNN + e];
                int j = s_j[wid][it * KNN + e];
                float rx = pj.x - pi.x, ry = pj.y - pi.y;
                float2 yv = *(const float2*)(d_Yb + j * HD + f0);
                m0 = fmaxf(m0, fmaf(inv, yv.x, fmaf(rx, wx0, fmaf(ry, wy0, be0))));
                m1 = fmaxf(m1, fmaf(inv, yv.y, fmaf(rx, wx1, fmaf(ry, wy1, be1))));
            }
            int r = wid * 4 + half * 2 + it;
            s_z[r * ZPAD + f0] = fmaxf(m0, 0.f);
            s_z[r * ZPAD + f1] = fmaxf(m1, 0.f);
        }
        __syncwarp();
    }
    __syncthreads();
    block_stats(s_z, s_red, blockIdx.x);
    if (tid < HD) {
        float m = s_z[tid];
#pragma unroll
        for (int r = 1; r < 32; r++) m = fmaxf(m, s_z[r * ZPAD + tid]);
        int g = blockIdx.x >> 6;
        atomicMax(&d_pool[g * HD + tid], __float_as_int(m));
    }
}

// ---------------------------------------------------------------------------
// head: normalize pooled max on the fly; MLP -> out[64,2]
// ---------------------------------------------------------------------------
__global__ __launch_bounds__(128) void head_kernel(const float* __restrict__ Wl1,
                                                   const float* __restrict__ bl1,
                                                   const float* __restrict__ Wl2,
                                                   const float* __restrict__ bl2,
                                                   float* __restrict__ out) {
    __shared__ float t1[BGR * HD];
    __shared__ float sW[HD * HD];
    __shared__ float s_mean[64];
    int tid = threadIdx.x;
    float inv = d_scaleInv;

    if (tid < HD) s_mean[tid] = d_mean[tid];
    const float4* W4 = (const float4*)Wl1;
    float4* sW4 = (float4*)sW;
    for (int i = tid; i < HD * HD / 4; i += 128) sW4[i] = W4[i];
    __syncthreads();

    int g = tid >> 1, half = tid & 1;
    float acc[32];
#pragma unroll
    for (int c = 0; c < 32; c++) acc[c] = bl1[half * 32 + c];
    for (int k = 0; k < HD; k++) {
        float h = (__int_as_float(d_pool[g * HD + k]) - s_mean[k]) * inv;
        const float* wrow = sW + k * HD + half * 32;
#pragma unroll
        for (int c = 0; c < 32; c++) acc[c] = fmaf(h, wrow[c], acc[c]);
    }
#pragma unroll
    for (int c = 0; c < 32; c++) t1[g * HD + half * 32 + c] = fmaxf(acc[c], 0.f);
    __syncthreads();

    int gg = tid >> 1, o = tid & 1;
    float s = bl2[o];
    for (int k = 0; k < HD; k++) s = fmaf(t1[gg * HD + k], Wl2[k * 2 + o], s);
    out[gg * 2 + o] = s;
}

// ---------------------------------------------------------------------------
// launch — capture index 3 = convA (FFMA epilogue + 2-node staging)
// ---------------------------------------------------------------------------
extern "C" void kernel_launch(void* const* d_in, const int* in_sizes, int n_in,
                              void* d_out, int out_size) {
    const float2* pos = (const float2*)d_in[0];
    const float* W1  = (const float*)d_in[2];
    const float* b1  = (const float*)d_in[3];
    const float* W2  = (const float*)d_in[4];
    const float* b2  = (const float*)d_in[5];
    const float* W3  = (const float*)d_in[6];
    const float* b3  = (const float*)d_in[7];
    const float* Wl1 = (const float*)d_in[8];
    const float* bl1 = (const float*)d_in[9];
    const float* Wl2 = (const float*)d_in[10];
    const float* bl2 = (const float*)d_in[11];
    float* out = (float*)d_out;

    init_kernel<<<16, 256>>>();                        // 0
    reorder_kernel<<<BGR, 256>>>(pos);                 // 1
    knn_kernel<<<BGR * 8, 256>>>();                    // 2
    convA_kernel<<<CONV_BLOCKS, 256>>>(W1, b1, W2);    // 3  <- profiled
    redstat_kernel<<<65, 256>>>(W2, b2);               // 4
    convB_kernel<<<CONV_BLOCKS, 256>>>(W2, W3);        // 5
    redstat_kernel<<<65, 256>>>(W3, b3);               // 6
    convC_kernel<<<CONV_BLOCKS, 256>>>(W3);            // 7
    redstat_kernel<<<65, 256>>>(nullptr, nullptr);     // 8
    head_kernel<<<1, 128>>>(Wl1, bl1, Wl2, bl2, out);  // 9
}